// round 11
// baseline (speedup 1.0000x reference)
#include <cuda_runtime.h>
#include <cuda_fp16.h>
#include <math.h>
#include <stdint.h>

// ---------------------------------------------------------------------------
// Problem constants
// ---------------------------------------------------------------------------
#define BB 8
#define TT 1024
#define DD 1024
#define HH 16
#define HD 64
#define FF 4096
#define MROWS (BB * TT)          // 8192
#define QS (3 * DD)              // packed QKV row stride
#define LN_EPS 1e-5f

// ---------------------------------------------------------------------------
// Scratch (__device__ globals; allocation-free rule)
// ---------------------------------------------------------------------------
__device__ float  g_hln1 [MROWS * DD];
__device__ __half g_hln1t[MROWS * DD];
__device__ __half g_qkv  [MROWS * QS];
__device__ __half g_ctx  [MROWS * DD];
__device__ float  g_h    [MROWS * DD];
__device__ float  g_h2   [MROWS * DD];
__device__ __half g_h2t  [MROWS * DD];
__device__ __half g_ff   [MROWS * FF];
__device__ __half g_Wqkv [3 * DD * DD];
__device__ __half g_WoT  [DD * DD];
__device__ __half g_W1T  [FF * DD];
__device__ __half g_W2T  [DD * FF];

// ---------------------------------------------------------------------------
// Helpers
// ---------------------------------------------------------------------------
__device__ __forceinline__ uint32_t smem_u32(const void* p) {
    uint32_t a;
    asm("{ .reg .u64 t; cvta.to.shared.u64 t, %1; cvt.u32.u64 %0, t; }"
        : "=r"(a) : "l"(p));
    return a;
}

__device__ __forceinline__ void cp_async16(uint32_t saddr, const void* gaddr) {
    asm volatile("cp.async.cg.shared.global [%0], [%1], 16;\n"
                 :: "r"(saddr), "l"(gaddr) : "memory");
}
#define CP_COMMIT() asm volatile("cp.async.commit_group;\n" ::: "memory")

__device__ __forceinline__ void mma_f16(float c[4], const uint32_t a[4],
                                        const uint32_t b[2]) {
    asm volatile(
        "mma.sync.aligned.m16n8k16.row.col.f32.f16.f16.f32 "
        "{%0,%1,%2,%3}, {%4,%5,%6,%7}, {%8,%9}, {%0,%1,%2,%3};"
        : "+f"(c[0]), "+f"(c[1]), "+f"(c[2]), "+f"(c[3])
        : "r"(a[0]), "r"(a[1]), "r"(a[2]), "r"(a[3]),
          "r"(b[0]), "r"(b[1]));
}

// fp16 accumulate variant (rt=8 hypothesis)
__device__ __forceinline__ void mma_f16acc(uint32_t c[2], const uint32_t a[4],
                                           const uint32_t b[2]) {
    asm volatile(
        "mma.sync.aligned.m16n8k16.row.col.f16.f16.f16.f16 "
        "{%0,%1}, {%2,%3,%4,%5}, {%6,%7}, {%0,%1};"
        : "+r"(c[0]), "+r"(c[1])
        : "r"(a[0]), "r"(a[1]), "r"(a[2]), "r"(a[3]),
          "r"(b[0]), "r"(b[1]));
}

__device__ __forceinline__ void ldsm_x4(uint32_t r[4], uint32_t saddr) {
    asm volatile(
        "ldmatrix.sync.aligned.m8n8.x4.shared.b16 {%0,%1,%2,%3}, [%4];"
        : "=r"(r[0]), "=r"(r[1]), "=r"(r[2]), "=r"(r[3]) : "r"(saddr));
}

__device__ __forceinline__ void ldsm_x4_trans(uint32_t r[4], uint32_t saddr) {
    asm volatile(
        "ldmatrix.sync.aligned.m8n8.x4.trans.shared.b16 {%0,%1,%2,%3}, [%4];"
        : "=r"(r[0]), "=r"(r[1]), "=r"(r[2]), "=r"(r[3]) : "r"(saddr));
}

// ---------------------------------------------------------------------------
// One kernel: transpose+half-convert ALL weights (12288 32x32 tiles)
// ---------------------------------------------------------------------------
__global__ void transpose_all_kernel(const float* __restrict__ Wq,
                                     const float* __restrict__ Wk,
                                     const float* __restrict__ Wv,
                                     const float* __restrict__ Wo,
                                     const float* __restrict__ W1,
                                     const float* __restrict__ W2,
                                     __half* __restrict__ Wqkv,
                                     __half* __restrict__ WoT,
                                     __half* __restrict__ W1T,
                                     __half* __restrict__ W2T)
{
    __shared__ float t[32][33];
    const int tblk = blockIdx.x;

    const float* in; __half* out; int K, N, local;
    if (tblk < 3072) {
        const int seg = tblk >> 10;
        in  = (seg == 0) ? Wq : (seg == 1) ? Wk : Wv;
        out = Wqkv + (size_t)seg * DD * DD;
        K = DD; N = DD; local = tblk & 1023;
    } else if (tblk < 4096) {
        in = Wo; out = WoT; K = DD; N = DD; local = tblk - 3072;
    } else if (tblk < 8192) {
        in = W1; out = W1T; K = DD; N = FF; local = tblk - 4096;
    } else {
        in = W2; out = W2T; K = FF; N = DD; local = tblk - 8192;
    }
    const int ntn = N >> 5;
    const int n0 = (local % ntn) * 32;
    const int k0 = (local / ntn) * 32;

    for (int i = threadIdx.y; i < 32; i += 8)
        t[i][threadIdx.x] = in[(size_t)(k0 + i) * N + n0 + threadIdx.x];
    __syncthreads();
    for (int i = threadIdx.y; i < 32; i += 8)
        out[(size_t)(n0 + i) * K + k0 + threadIdx.x] =
            __float2half_rn(t[threadIdx.x][i]);
}

// ---------------------------------------------------------------------------
// LayerNorm (unbiased var, ddof=1), dual output: fp32 + half
// ---------------------------------------------------------------------------
__global__ void ln_kernel(const float* __restrict__ src,
                          const float* __restrict__ gamma,
                          const float* __restrict__ beta,
                          float* __restrict__ dst,
                          __half* __restrict__ dsth)
{
    const int row = blockIdx.x;
    const int tid = threadIdx.x;
    const float4* in4 = reinterpret_cast<const float4*>(src + (size_t)row * DD);
    float4* out4 = reinterpret_cast<float4*>(dst + (size_t)row * DD);
    __half2* outh = reinterpret_cast<__half2*>(dsth + (size_t)row * DD);
    const float4* g4 = reinterpret_cast<const float4*>(gamma);
    const float4* b4 = reinterpret_cast<const float4*>(beta);

    float4 x = in4[tid];
    float s  = x.x + x.y + x.z + x.w;
    float ss = x.x * x.x + x.y * x.y + x.z * x.z + x.w * x.w;
    for (int o = 16; o; o >>= 1) {
        s  += __shfl_xor_sync(0xffffffffu, s, o);
        ss += __shfl_xor_sync(0xffffffffu, ss, o);
    }
    __shared__ float rs[8], rss[8];
    __shared__ float smean, srstd;
    const int warp = tid >> 5, lane = tid & 31;
    if (lane == 0) { rs[warp] = s; rss[warp] = ss; }
    __syncthreads();
    if (warp == 0) {
        float a = (lane < 8) ? rs[lane] : 0.0f;
        float b = (lane < 8) ? rss[lane] : 0.0f;
        for (int o = 4; o; o >>= 1) {
            a += __shfl_xor_sync(0xffffffffu, a, o);
            b += __shfl_xor_sync(0xffffffffu, b, o);
        }
        if (lane == 0) {
            float mean = a * (1.0f / DD);
            float var  = (b - (float)DD * mean * mean) * (1.0f / (DD - 1));
            smean = mean;
            srstd = rsqrtf(var + LN_EPS);
        }
    }
    __syncthreads();
    const float mean = smean, rstd = srstd;
    float4 gv = g4[tid], bv = b4[tid];
    float4 o;
    o.x = (x.x - mean) * rstd * gv.x + bv.x;
    o.y = (x.y - mean) * rstd * gv.y + bv.y;
    o.z = (x.z - mean) * rstd * gv.z + bv.z;
    o.w = (x.w - mean) * rstd * gv.w + bv.w;
    out4[tid] = o;
    outh[2 * tid]     = __floats2half2_rn(o.x, o.y);
    outh[2 * tid + 1] = __floats2half2_rn(o.z, o.w);
}

// ---------------------------------------------------------------------------
// fp16 mma GEMM, 3-stage pipeline, ldmatrix fragment loads.
// C[M,N] = A[M,K] @ B^T (B [N,K] K-major, half) + bias
// MODE 1: half out, gelu(acc+bias), fp16-accum mainloop w/ chunk promotion
// MODE 2: float out, acc+bias+Res (fp32 accum)
// MODE 3: half out, segmented bias (QKV, fp32 accum)
// ---------------------------------------------------------------------------
#define GTILE_B (128 * 144)
#define GSTAGE_B (2 * GTILE_B)          // A then B, per stage: 36864
#define GSMEM_B (3 * GSTAGE_B)          // 110592

template <int MODE>
__global__ __launch_bounds__(256, 2)
void gemm_h(const __half* __restrict__ A, const __half* __restrict__ B,
            const float* __restrict__ bias, void* __restrict__ Cv,
            const float* __restrict__ Res,
            const float* __restrict__ bias2, const float* __restrict__ bias3,
            int M, int N, int K)
{
    extern __shared__ char dynsmem[];
    const int tid = threadIdx.x;
    const int wid = tid >> 5, lane = tid & 31;
    const int bx = blockIdx.x, by = blockIdx.y;

    const int warp_m = (wid & 3) * 32;
    const int warp_n = (wid >> 2) * 64;
    const int lr = lane >> 2;
    const int lc = lane & 3;

    const int lm_m   = lane >> 3;
    const int lm_row = (lm_m & 1) * 8 + (lane & 7);
    const int lm_kb  = (lm_m >> 1) * 16;

    const uint32_t sbase = smem_u32(dynsmem);

    const int g_r  = tid >> 1;
    const int g_h  = tid & 1;
    const __half* gA = A + (size_t)(by * 128 + g_r) * K + g_h * 32;
    const __half* gB = B + (size_t)(bx * 128 + g_r) * K + g_h * 32;
    const uint32_t s_off = (uint32_t)(g_r * 144 + g_h * 64);

    const int NITER = K >> 6;

    auto stage = [&](int s) {
        const uint32_t base = sbase + (uint32_t)(s % 3) * GSTAGE_B;
        const int k0 = s << 6;
#pragma unroll
        for (int p = 0; p < 4; p++) {
            cp_async16(base + s_off + p * 16, gA + k0 + p * 8);
            cp_async16(base + GTILE_B + s_off + p * 16, gB + k0 + p * 8);
        }
        CP_COMMIT();
    };

    float c[2][8][4];
#pragma unroll
    for (int mt = 0; mt < 2; mt++)
#pragma unroll
        for (int nt = 0; nt < 8; nt++)
#pragma unroll
            for (int r = 0; r < 4; r++) c[mt][nt][r] = 0.0f;

    stage(0);
    stage(1);

    for (int i = 0; i < NITER; i++) {
        if (i < NITER - 1)
            asm volatile("cp.async.wait_group 1;\n" ::: "memory");
        else
            asm volatile("cp.async.wait_group 0;\n" ::: "memory");
        __syncthreads();

        if (i + 2 < NITER) stage(i + 2);

        const uint32_t sA_b = sbase + (uint32_t)(i % 3) * GSTAGE_B;
        const uint32_t sB_b = sA_b + GTILE_B;

        if (MODE == 1) {
            // fp16-accumulate chunk, promote to fp32 once per chunk
#pragma unroll
            for (int mt = 0; mt < 2; mt++) {
                uint32_t hc[8][2];
#pragma unroll
                for (int nt = 0; nt < 8; nt++) {
                    hc[nt][0] = 0u; hc[nt][1] = 0u;
                }
#pragma unroll
                for (int ks = 0; ks < 4; ks++) {
                    const uint32_t koff = (uint32_t)(ks * 32 + lm_kb);
                    uint32_t a[4];
                    ldsm_x4(a, sA_b + (uint32_t)((warp_m + mt * 16 + lm_row)
                                                 * 144) + koff);
#pragma unroll
                    for (int g = 0; g < 4; g++) {
                        uint32_t kf[4];
                        ldsm_x4(kf, sB_b + (uint32_t)((warp_n + g * 16 + lm_row)
                                                      * 144) + koff);
                        uint32_t b0[2] = {kf[0], kf[2]};
                        uint32_t b1[2] = {kf[1], kf[3]};
                        mma_f16acc(hc[2 * g],     a, b0);
                        mma_f16acc(hc[2 * g + 1], a, b1);
                    }
                }
#pragma unroll
                for (int nt = 0; nt < 8; nt++) {
                    float2 f0 = __half22float2(
                        *reinterpret_cast<__half2*>(&hc[nt][0]));
                    float2 f1 = __half22float2(
                        *reinterpret_cast<__half2*>(&hc[nt][1]));
                    c[mt][nt][0] += f0.x; c[mt][nt][1] += f0.y;
                    c[mt][nt][2] += f1.x; c[mt][nt][3] += f1.y;
                }
            }
        } else {
            // fp32-accumulate path (round-10)
#pragma unroll
            for (int ks = 0; ks < 4; ks++) {
                const uint32_t koff = (uint32_t)(ks * 32 + lm_kb);
                uint32_t a[2][4];
                ldsm_x4(a[0], sA_b + (uint32_t)((warp_m + lm_row) * 144) + koff);
                ldsm_x4(a[1], sA_b + (uint32_t)((warp_m + 16 + lm_row) * 144)
                              + koff);
                uint32_t b[8][2];
#pragma unroll
                for (int g = 0; g < 4; g++) {
                    uint32_t kf[4];
                    ldsm_x4(kf, sB_b + (uint32_t)((warp_n + g * 16 + lm_row)
                                                  * 144) + koff);
                    b[2 * g][0] = kf[0];     b[2 * g][1] = kf[2];
                    b[2 * g + 1][0] = kf[1]; b[2 * g + 1][1] = kf[3];
                }
#pragma unroll
                for (int mt = 0; mt < 2; mt++)
#pragma unroll
                    for (int nt = 0; nt < 8; nt++)
                        mma_f16(c[mt][nt], a[mt], b[nt]);
            }
        }
    }

    const float* bb = bias;
    if (MODE == 3) {
        const int seg = (bx * 128) >> 10;
        bb = (seg == 0) ? bias : (seg == 1) ? bias2 : bias3;
    }

    const float inv_s2 = 0.70710678118654752f;
    __half* Ch = reinterpret_cast<__half*>(Cv);
    float* Cf = reinterpret_cast<float*>(Cv);
#pragma unroll
    for (int mt = 0; mt < 2; mt++) {
#pragma unroll
        for (int rh = 0; rh < 2; rh++) {
            const int m = by * 128 + warp_m + mt * 16 + lr + rh * 8;
#pragma unroll
            for (int nt = 0; nt < 8; nt++) {
                const int n = bx * 128 + warp_n + nt * 8 + 2 * lc;
                const int nb = (MODE == 3) ? (n & 1023) : n;
                float v0 = c[mt][nt][rh * 2 + 0] + bb[nb];
                float v1 = c[mt][nt][rh * 2 + 1] + bb[nb + 1];
                if (MODE == 1) {
                    v0 = 0.5f * v0 * (1.0f + erff(v0 * inv_s2));
                    v1 = 0.5f * v1 * (1.0f + erff(v1 * inv_s2));
                }
                if (MODE == 2) {
                    float2 rv = *reinterpret_cast<const float2*>(
                        Res + (size_t)m * N + n);
                    v0 += rv.x; v1 += rv.y;
                    *reinterpret_cast<float2*>(Cf + (size_t)m * N + n) =
                        make_float2(v0, v1);
                } else {
                    *reinterpret_cast<__half2*>(Ch + (size_t)m * N + n) =
                        __floats2half2_rn(v0, v1);
                }
            }
        }
    }
}

// ---------------------------------------------------------------------------
// fp16 flash attention (round-9 version, 3-buffer prefetch-first pipeline)
// ---------------------------------------------------------------------------
#define AQ_B 18432                // 128 x 144B Q tile
#define AKT_B 9216                // one 64 x 144B K or V tile
#define AKV_B (2 * AKT_B)         // K+V per buffer
#define ASMEM_B (AQ_B + 3 * AKV_B)   // 73728

__global__ __launch_bounds__(256, 2)
void attn_h_kernel(const __half* __restrict__ QKV,
                   __half* __restrict__ O)
{
    extern __shared__ char asmem[];

    const int bh = blockIdx.x;
    const int b  = bh / HH;
    const int h  = bh % HH;
    const int q0 = blockIdx.y * 128;
    const size_t baseq = (size_t)b * TT * QS + (size_t)h * HD;
    const size_t basek = baseq + DD;
    const size_t basev = baseq + 2 * DD;
    const size_t baseo = (size_t)b * TT * DD + (size_t)h * HD;

    const int tid = threadIdx.x;
    const int warp = tid >> 5, lane = tid & 31;
    const int lr = lane >> 2, lc = lane & 3;
    const int qr = warp * 16;

    const uint32_t sQ_b = smem_u32(asmem);
    const uint32_t sB0_b = sQ_b + AQ_B;

    const int lm_m   = lane >> 3;
    const int lm_row = (lm_m & 1) * 8 + (lane & 7);
    const int lm_kb  = (lm_m >> 1) * 16;

    const int st_r = tid >> 2;
    const int st_q = tid & 3;
    auto stage_tile = [&](uint32_t dstbase, const __half* gsrc) {
        const uint32_t d = dstbase + (uint32_t)(st_r * 144 + st_q * 32);
        const __half* g = gsrc + (size_t)st_r * QS + st_q * 16;
        cp_async16(d, g);
        cp_async16(d + 16, g + 8);
    };

    stage_tile(sQ_b,         QKV + baseq + (size_t)q0 * QS);
    stage_tile(sQ_b + AKT_B, QKV + baseq + (size_t)(q0 + 64) * QS);
    stage_tile(sB0_b,         QKV + basek);
    stage_tile(sB0_b + AKT_B, QKV + basev);
    CP_COMMIT();
    stage_tile(sB0_b + AKV_B,         QKV + basek + (size_t)64 * QS);
    stage_tile(sB0_b + AKV_B + AKT_B, QKV + basev + (size_t)64 * QS);
    CP_COMMIT();

    float m0 = -INFINITY, m1 = -INFINITY;
    float l0 = 0.0f, l1 = 0.0f;
    float o[8][4];
#pragma unroll
    for (int nt = 0; nt < 8; nt++)
#pragma unroll
        for (int j = 0; j < 4; j++) o[nt][j] = 0.0f;

    uint32_t qf[4][4];

    const int NT = TT / 64;
    for (int t = 0; t < NT; t++) {
        if (t < NT - 1)
            asm volatile("cp.async.wait_group 1;\n" ::: "memory");
        else
            asm volatile("cp.async.wait_group 0;\n" ::: "memory");
        __syncthreads();

        if (t + 2 < NT) {
            const uint32_t dst = sB0_b + (uint32_t)((t + 2) % 3) * AKV_B;
            stage_tile(dst,         QKV + basek + (size_t)((t + 2) * 64) * QS);
            stage_tile(dst + AKT_B, QKV + basev + (size_t)((t + 2) * 64) * QS);
            CP_COMMIT();
        }

        if (t == 0) {
#pragma unroll
            for (int ks = 0; ks < 4; ks++)
                ldsm_x4(qf[ks], sQ_b + (uint32_t)((qr + lm_row) * 144 +
                                                  ks * 32 + lm_kb));
        }

        const uint32_t sK_b = sB0_b + (uint32_t)(t % 3) * AKV_B;
        const uint32_t sV_b = sK_b + AKT_B;

        float s[8][4];
#pragma unroll
        for (int nt = 0; nt < 8; nt++)
#pragma unroll
            for (int j = 0; j < 4; j++) s[nt][j] = 0.0f;

#pragma unroll
        for (int ks = 0; ks < 4; ks++) {
#pragma unroll
            for (int g = 0; g < 4; g++) {
                uint32_t kf[4];
                ldsm_x4(kf, sK_b + (uint32_t)((g * 16 + lm_row) * 144 +
                                              ks * 32 + lm_kb));
                uint32_t b0[2] = {kf[0], kf[2]};
                uint32_t b1[2] = {kf[1], kf[3]};
                mma_f16(s[2 * g],     qf[ks], b0);
                mma_f16(s[2 * g + 1], qf[ks], b1);
            }
        }

        float mx0 = -INFINITY, mx1 = -INFINITY;
#pragma unroll
        for (int nt = 0; nt < 8; nt++) {
            s[nt][0] *= 0.125f; s[nt][1] *= 0.125f;
            s[nt][2] *= 0.125f; s[nt][3] *= 0.125f;
            mx0 = fmaxf(mx0, fmaxf(s[nt][0], s[nt][1]));
            mx1 = fmaxf(mx1, fmaxf(s[nt][2], s[nt][3]));
        }
        mx0 = fmaxf(mx0, __shfl_xor_sync(0xffffffffu, mx0, 1));
        mx0 = fmaxf(mx0, __shfl_xor_sync(0xffffffffu, mx0, 2));
        mx1 = fmaxf(mx1, __shfl_xor_sync(0xffffffffu, mx1, 1));
        mx1 = fmaxf(mx1, __shfl_xor_sync(0xffffffffu, mx1, 2));

        const float nm0 = fmaxf(m0, mx0), nm1 = fmaxf(m1, mx1);
        const float corr0 = __expf(m0 - nm0), corr1 = __expf(m1 - nm1);
        m0 = nm0; m1 = nm1;

        float ls0 = 0.0f, ls1 = 0.0f;
#pragma unroll
        for (int nt = 0; nt < 8; nt++) {
            s[nt][0] = __expf(s[nt][0] - nm0);
            s[nt][1] = __expf(s[nt][1] - nm0);
            s[nt][2] = __expf(s[nt][2] - nm1);
            s[nt][3] = __expf(s[nt][3] - nm1);
            ls0 += s[nt][0] + s[nt][1];
            ls1 += s[nt][2] + s[nt][3];
        }
        ls0 += __shfl_xor_sync(0xffffffffu, ls0, 1);
        ls0 += __shfl_xor_sync(0xffffffffu, ls0, 2);
        ls1 += __shfl_xor_sync(0xffffffffu, ls1, 1);
        ls1 += __shfl_xor_sync(0xffffffffu, ls1, 2);
        l0 = l0 * corr0 + ls0;
        l1 = l1 * corr1 + ls1;

#pragma unroll
        for (int nt = 0; nt < 8; nt++) {
            o[nt][0] *= corr0; o[nt][1] *= corr0;
            o[nt][2] *= corr1; o[nt][3] *= corr1;
        }

        const int key = (lane & 7) + ((lane >> 3) & 1) * 8;
#pragma unroll
        for (int ks = 0; ks < 4; ks++) {
            uint32_t pa[4];
            __half2 hh;
            hh = __floats2half2_rn(s[2 * ks][0], s[2 * ks][1]);
            pa[0] = *reinterpret_cast<uint32_t*>(&hh);
            hh = __floats2half2_rn(s[2 * ks][2], s[2 * ks][3]);
            pa[1] = *reinterpret_cast<uint32_t*>(&hh);
            hh = __floats2half2_rn(s[2 * ks + 1][0], s[2 * ks + 1][1]);
            pa[2] = *reinterpret_cast<uint32_t*>(&hh);
            hh = __floats2half2_rn(s[2 * ks + 1][2], s[2 * ks + 1][3]);
            pa[3] = *reinterpret_cast<uint32_t*>(&hh);

#pragma unroll
            for (int ntp = 0; ntp < 4; ntp++) {
                uint32_t r[4];
                const uint32_t addr = sV_b +
                    (uint32_t)((ks * 16 + key) * 144 + ntp * 32 +
                               ((lane >> 4) & 1) * 16);
                ldsm_x4_trans(r, addr);
                uint32_t b0[2] = {r[0], r[1]};
                uint32_t b1[2] = {r[2], r[3]};
                mma_f16(o[2 * ntp],     pa, b0);
                mma_f16(o[2 * ntp + 1], pa, b1);
            }
        }
    }

    const float inv0 = 1.0f / l0, inv1 = 1.0f / l1;
    const size_t row0 = baseo + (size_t)(q0 + qr + lr) * DD;
    const size_t row1 = baseo + (size_t)(q0 + qr + lr + 8) * DD;
#pragma unroll
    for (int nt = 0; nt < 8; nt++) {
        const int col = nt * 8 + 2 * lc;
        *reinterpret_cast<__half2*>(O + row0 + col) =
            __floats2half2_rn(o[nt][0] * inv0, o[nt][1] * inv0);
        *reinterpret_cast<__half2*>(O + row1 + col) =
            __floats2half2_rn(o[nt][2] * inv1, o[nt][3] * inv1);
    }
}

// ---------------------------------------------------------------------------
// Launch
// ---------------------------------------------------------------------------
template <typename T>
static T* symT(const void* symbol)
{
    void* p = nullptr;
    cudaGetSymbolAddress(&p, symbol);
    return reinterpret_cast<T*>(p);
}

extern "C" void kernel_launch(void* const* d_in, const int* in_sizes, int n_in,
                              void* d_out, int out_size)
{
    const float* x  = (const float*)d_in[0];
    const float* Wq = (const float*)d_in[1];  const float* bq = (const float*)d_in[2];
    const float* Wk = (const float*)d_in[3];  const float* bk = (const float*)d_in[4];
    const float* Wv = (const float*)d_in[5];  const float* bv = (const float*)d_in[6];
    const float* Wo = (const float*)d_in[7];  const float* bo = (const float*)d_in[8];
    const float* W1 = (const float*)d_in[9];  const float* b1 = (const float*)d_in[10];
    const float* W2 = (const float*)d_in[11]; const float* b2 = (const float*)d_in[12];
    const float* g1 = (const float*)d_in[13]; const float* be1 = (const float*)d_in[14];
    const float* g2 = (const float*)d_in[15]; const float* be2 = (const float*)d_in[16];
    float* out = (float*)d_out;

    float*  hln1  = symT<float>(g_hln1);
    __half* hln1t = symT<__half>(g_hln1t);
    __half* qkv   = symT<__half>(g_qkv);
    __half* ctx   = symT<__half>(g_ctx);
    float*  hb    = symT<float>(g_h);
    float*  h2b   = symT<float>(g_h2);
    __half* h2t   = symT<__half>(g_h2t);
    __half* ffb   = symT<__half>(g_ff);
    __half* Wqkv = symT<__half>(g_Wqkv);
    __half* WoT  = symT<__half>(g_WoT);
    __half* W1T  = symT<__half>(g_W1T);
    __half* W2T  = symT<__half>(g_W2T);

    cudaFuncSetAttribute(gemm_h<1>, cudaFuncAttributeMaxDynamicSharedMemorySize, GSMEM_B);
    cudaFuncSetAttribute(gemm_h<2>, cudaFuncAttributeMaxDynamicSharedMemorySize, GSMEM_B);
    cudaFuncSetAttribute(gemm_h<3>, cudaFuncAttributeMaxDynamicSharedMemorySize, GSMEM_B);
    cudaFuncSetAttribute(attn_h_kernel, cudaFuncAttributeMaxDynamicSharedMemorySize, ASMEM_B);

    // 0. all weight transposes in one launch
    transpose_all_kernel<<<12288, dim3(32, 8)>>>(
        Wq, Wk, Wv, Wo, W1, W2, Wqkv, WoT, W1T, W2T);

    // 1. LN1 (fp32 + half)
    ln_kernel<<<MROWS, 256>>>(x, g1, be1, hln1, hln1t);

    // 2. fused QKV projection -> packed [M][3072]
    {
        dim3 grid(QS / 128, MROWS / 128);
        gemm_h<3><<<grid, 256, GSMEM_B>>>(hln1t, Wqkv, bq, qkv, nullptr,
                                          bk, bv, MROWS, QS, DD);
    }

    // 3. attention (128 q-rows per block, 8 warps)
    {
        dim3 grid(BB * HH, TT / 128);
        attn_h_kernel<<<grid, 256, ASMEM_B>>>(qkv, ctx);
    }

    // 4. output projection + residual (fp32 out)
    {
        dim3 grid(DD / 128, MROWS / 128);
        gemm_h<2><<<grid, 256, GSMEM_B>>>(ctx, WoT, bo, hb, hln1,
                                          nullptr, nullptr, MROWS, DD, DD);
    }

    // 5. LN2
    ln_kernel<<<MROWS, 256>>>(hb, g2, be2, h2b, h2t);

    // 6. FFN up + exact GELU (half out, fp16-accum mainloop)
    {
        dim3 grid(FF / 128, MROWS / 128);
        gemm_h<1><<<grid, 256, GSMEM_B>>>(h2t, W1T, b1, ffb, nullptr,
                                          nullptr, nullptr, MROWS, FF, DD);
    }

    // 7. FFN down + bias + residual -> out (fp32)
    {
        dim3 grid(DD / 128, MROWS / 128);
        gemm_h<2><<<grid, 256, GSMEM_B>>>(ffb, W2T, b2, out, h2b,
                                          nullptr, nullptr, MROWS, DD, FF);
    }
}

// round 12
// speedup vs baseline: 1.0457x; 1.0457x over previous
#include <cuda_runtime.h>
#include <cuda_fp16.h>
#include <math.h>
#include <stdint.h>

// ---------------------------------------------------------------------------
// Problem constants
// ---------------------------------------------------------------------------
#define BB 8
#define TT 1024
#define DD 1024
#define HH 16
#define HD 64
#define FF 4096
#define MROWS (BB * TT)          // 8192
#define QS (3 * DD)              // packed QKV row stride
#define LN_EPS 1e-5f

// ---------------------------------------------------------------------------
// Scratch (__device__ globals; allocation-free rule)
// ---------------------------------------------------------------------------
__device__ float  g_hln1 [MROWS * DD];
__device__ __half g_hln1t[MROWS * DD];
__device__ __half g_qkv  [MROWS * QS];
__device__ __half g_ctx  [MROWS * DD];
__device__ float  g_h    [MROWS * DD];
__device__ float  g_h2   [MROWS * DD];
__device__ __half g_h2t  [MROWS * DD];
__device__ __half g_ff   [MROWS * FF];
__device__ __half g_Wqkv [3 * DD * DD];
__device__ __half g_WoT  [DD * DD];
__device__ __half g_W1T  [FF * DD];
__device__ __half g_W2T  [DD * FF];

// ---------------------------------------------------------------------------
// Helpers
// ---------------------------------------------------------------------------
__device__ __forceinline__ uint32_t smem_u32(const void* p) {
    uint32_t a;
    asm("{ .reg .u64 t; cvta.to.shared.u64 t, %1; cvt.u32.u64 %0, t; }"
        : "=r"(a) : "l"(p));
    return a;
}

__device__ __forceinline__ void cp_async16(uint32_t saddr, const void* gaddr) {
    asm volatile("cp.async.cg.shared.global [%0], [%1], 16;\n"
                 :: "r"(saddr), "l"(gaddr) : "memory");
}
#define CP_COMMIT() asm volatile("cp.async.commit_group;\n" ::: "memory")

__device__ __forceinline__ void mma_f16(float c[4], const uint32_t a[4],
                                        const uint32_t b[2]) {
    asm volatile(
        "mma.sync.aligned.m16n8k16.row.col.f32.f16.f16.f32 "
        "{%0,%1,%2,%3}, {%4,%5,%6,%7}, {%8,%9}, {%0,%1,%2,%3};"
        : "+f"(c[0]), "+f"(c[1]), "+f"(c[2]), "+f"(c[3])
        : "r"(a[0]), "r"(a[1]), "r"(a[2]), "r"(a[3]),
          "r"(b[0]), "r"(b[1]));
}

__device__ __forceinline__ void ldsm_x4(uint32_t r[4], uint32_t saddr) {
    asm volatile(
        "ldmatrix.sync.aligned.m8n8.x4.shared.b16 {%0,%1,%2,%3}, [%4];"
        : "=r"(r[0]), "=r"(r[1]), "=r"(r[2]), "=r"(r[3]) : "r"(saddr));
}

__device__ __forceinline__ void ldsm_x4_trans(uint32_t r[4], uint32_t saddr) {
    asm volatile(
        "ldmatrix.sync.aligned.m8n8.x4.trans.shared.b16 {%0,%1,%2,%3}, [%4];"
        : "=r"(r[0]), "=r"(r[1]), "=r"(r[2]), "=r"(r[3]) : "r"(saddr));
}

// ---------------------------------------------------------------------------
// Fused prep kernel: LN1 (blocks 0..8191) + ALL weight transposes
// (blocks 8192..20479). The two halves are data-independent, so one launch
// overlaps them across the grid.
// ---------------------------------------------------------------------------
__global__ void prep_kernel(const float* __restrict__ x,
                            const float* __restrict__ gamma,
                            const float* __restrict__ beta,
                            float* __restrict__ dst,
                            __half* __restrict__ dsth,
                            const float* __restrict__ Wq,
                            const float* __restrict__ Wk,
                            const float* __restrict__ Wv,
                            const float* __restrict__ Wo,
                            const float* __restrict__ W1,
                            const float* __restrict__ W2,
                            __half* __restrict__ Wqkv,
                            __half* __restrict__ WoT,
                            __half* __restrict__ W1T,
                            __half* __restrict__ W2T)
{
    const int tid = threadIdx.x;

    if (blockIdx.x < MROWS) {
        // ---------------- LN1 row ----------------
        const int row = blockIdx.x;
        const float4* in4 = reinterpret_cast<const float4*>(x + (size_t)row * DD);
        float4* out4 = reinterpret_cast<float4*>(dst + (size_t)row * DD);
        __half2* outh = reinterpret_cast<__half2*>(dsth + (size_t)row * DD);
        const float4* g4 = reinterpret_cast<const float4*>(gamma);
        const float4* b4 = reinterpret_cast<const float4*>(beta);

        float4 xv = in4[tid];
        float s  = xv.x + xv.y + xv.z + xv.w;
        float ss = xv.x * xv.x + xv.y * xv.y + xv.z * xv.z + xv.w * xv.w;
        for (int o = 16; o; o >>= 1) {
            s  += __shfl_xor_sync(0xffffffffu, s, o);
            ss += __shfl_xor_sync(0xffffffffu, ss, o);
        }
        __shared__ float rs[8], rss[8];
        __shared__ float smean, srstd;
        const int warp = tid >> 5, lane = tid & 31;
        if (lane == 0) { rs[warp] = s; rss[warp] = ss; }
        __syncthreads();
        if (warp == 0) {
            float a = (lane < 8) ? rs[lane] : 0.0f;
            float b = (lane < 8) ? rss[lane] : 0.0f;
            for (int o = 4; o; o >>= 1) {
                a += __shfl_xor_sync(0xffffffffu, a, o);
                b += __shfl_xor_sync(0xffffffffu, b, o);
            }
            if (lane == 0) {
                float mean = a * (1.0f / DD);
                float var  = (b - (float)DD * mean * mean) * (1.0f / (DD - 1));
                smean = mean;
                srstd = rsqrtf(var + LN_EPS);
            }
        }
        __syncthreads();
        const float mean = smean, rstd = srstd;
        float4 gv = g4[tid], bv = b4[tid];
        float4 o;
        o.x = (xv.x - mean) * rstd * gv.x + bv.x;
        o.y = (xv.y - mean) * rstd * gv.y + bv.y;
        o.z = (xv.z - mean) * rstd * gv.z + bv.z;
        o.w = (xv.w - mean) * rstd * gv.w + bv.w;
        out4[tid] = o;
        outh[2 * tid]     = __floats2half2_rn(o.x, o.y);
        outh[2 * tid + 1] = __floats2half2_rn(o.z, o.w);
    } else {
        // ---------------- weight transpose tile ----------------
        __shared__ float t[32][33];
        const int tblk = blockIdx.x - MROWS;
        const int tx = tid & 31, ty = tid >> 5;   // 32 x 8

        const float* in; __half* out; int K, N, local;
        if (tblk < 3072) {
            const int seg = tblk >> 10;
            in  = (seg == 0) ? Wq : (seg == 1) ? Wk : Wv;
            out = Wqkv + (size_t)seg * DD * DD;
            K = DD; N = DD; local = tblk & 1023;
        } else if (tblk < 4096) {
            in = Wo; out = WoT; K = DD; N = DD; local = tblk - 3072;
        } else if (tblk < 8192) {
            in = W1; out = W1T; K = DD; N = FF; local = tblk - 4096;
        } else {
            in = W2; out = W2T; K = FF; N = DD; local = tblk - 8192;
        }
        const int ntn = N >> 5;
        const int n0 = (local % ntn) * 32;
        const int k0 = (local / ntn) * 32;

        for (int i = ty; i < 32; i += 8)
            t[i][tx] = in[(size_t)(k0 + i) * N + n0 + tx];
        __syncthreads();
        for (int i = ty; i < 32; i += 8)
            out[(size_t)(n0 + i) * K + k0 + tx] = __float2half_rn(t[tx][i]);
    }
}

// ---------------------------------------------------------------------------
// LayerNorm (unbiased var, ddof=1), dual output: fp32 + half   (LN2)
// ---------------------------------------------------------------------------
__global__ void ln_kernel(const float* __restrict__ src,
                          const float* __restrict__ gamma,
                          const float* __restrict__ beta,
                          float* __restrict__ dst,
                          __half* __restrict__ dsth)
{
    const int row = blockIdx.x;
    const int tid = threadIdx.x;
    const float4* in4 = reinterpret_cast<const float4*>(src + (size_t)row * DD);
    float4* out4 = reinterpret_cast<float4*>(dst + (size_t)row * DD);
    __half2* outh = reinterpret_cast<__half2*>(dsth + (size_t)row * DD);
    const float4* g4 = reinterpret_cast<const float4*>(gamma);
    const float4* b4 = reinterpret_cast<const float4*>(beta);

    float4 x = in4[tid];
    float s  = x.x + x.y + x.z + x.w;
    float ss = x.x * x.x + x.y * x.y + x.z * x.z + x.w * x.w;
    for (int o = 16; o; o >>= 1) {
        s  += __shfl_xor_sync(0xffffffffu, s, o);
        ss += __shfl_xor_sync(0xffffffffu, ss, o);
    }
    __shared__ float rs[8], rss[8];
    __shared__ float smean, srstd;
    const int warp = tid >> 5, lane = tid & 31;
    if (lane == 0) { rs[warp] = s; rss[warp] = ss; }
    __syncthreads();
    if (warp == 0) {
        float a = (lane < 8) ? rs[lane] : 0.0f;
        float b = (lane < 8) ? rss[lane] : 0.0f;
        for (int o = 4; o; o >>= 1) {
            a += __shfl_xor_sync(0xffffffffu, a, o);
            b += __shfl_xor_sync(0xffffffffu, b, o);
        }
        if (lane == 0) {
            float mean = a * (1.0f / DD);
            float var  = (b - (float)DD * mean * mean) * (1.0f / (DD - 1));
            smean = mean;
            srstd = rsqrtf(var + LN_EPS);
        }
    }
    __syncthreads();
    const float mean = smean, rstd = srstd;
    float4 gv = g4[tid], bv = b4[tid];
    float4 o;
    o.x = (x.x - mean) * rstd * gv.x + bv.x;
    o.y = (x.y - mean) * rstd * gv.y + bv.y;
    o.z = (x.z - mean) * rstd * gv.z + bv.z;
    o.w = (x.w - mean) * rstd * gv.w + bv.w;
    out4[tid] = o;
    outh[2 * tid]     = __floats2half2_rn(o.x, o.y);
    outh[2 * tid + 1] = __floats2half2_rn(o.z, o.w);
}

// ---------------------------------------------------------------------------
// fp16 mma GEMM, 3-stage pipeline, ldmatrix fragment loads (round-10 state).
// C[M,N] = A[M,K] @ B^T (B [N,K] K-major, half) + bias
// MODE 1: half out, gelu(acc+bias)   MODE 2: float out, acc+bias+Res
// MODE 3: half out, segmented bias (QKV)
// All modes: fp32 accumulate (fp16-acc experiment reverted: no rate gain).
// ---------------------------------------------------------------------------
#define GTILE_B (128 * 144)
#define GSTAGE_B (2 * GTILE_B)          // A then B, per stage: 36864
#define GSMEM_B (3 * GSTAGE_B)          // 110592

template <int MODE>
__global__ __launch_bounds__(256, 2)
void gemm_h(const __half* __restrict__ A, const __half* __restrict__ B,
            const float* __restrict__ bias, void* __restrict__ Cv,
            const float* __restrict__ Res,
            const float* __restrict__ bias2, const float* __restrict__ bias3,
            int M, int N, int K)
{
    extern __shared__ char dynsmem[];
    const int tid = threadIdx.x;
    const int wid = tid >> 5, lane = tid & 31;
    const int bx = blockIdx.x, by = blockIdx.y;

    const int warp_m = (wid & 3) * 32;
    const int warp_n = (wid >> 2) * 64;
    const int lr = lane >> 2;
    const int lc = lane & 3;

    const int lm_m   = lane >> 3;
    const int lm_row = (lm_m & 1) * 8 + (lane & 7);
    const int lm_kb  = (lm_m >> 1) * 16;

    const uint32_t sbase = smem_u32(dynsmem);

    const int g_r  = tid >> 1;
    const int g_h  = tid & 1;
    const __half* gA = A + (size_t)(by * 128 + g_r) * K + g_h * 32;
    const __half* gB = B + (size_t)(bx * 128 + g_r) * K + g_h * 32;
    const uint32_t s_off = (uint32_t)(g_r * 144 + g_h * 64);

    const int NITER = K >> 6;

    auto stage = [&](int s) {
        const uint32_t base = sbase + (uint32_t)(s % 3) * GSTAGE_B;
        const int k0 = s << 6;
#pragma unroll
        for (int p = 0; p < 4; p++) {
            cp_async16(base + s_off + p * 16, gA + k0 + p * 8);
            cp_async16(base + GTILE_B + s_off + p * 16, gB + k0 + p * 8);
        }
        CP_COMMIT();
    };

    float c[2][8][4];
#pragma unroll
    for (int mt = 0; mt < 2; mt++)
#pragma unroll
        for (int nt = 0; nt < 8; nt++)
#pragma unroll
            for (int r = 0; r < 4; r++) c[mt][nt][r] = 0.0f;

    stage(0);
    stage(1);

    for (int i = 0; i < NITER; i++) {
        if (i < NITER - 1)
            asm volatile("cp.async.wait_group 1;\n" ::: "memory");
        else
            asm volatile("cp.async.wait_group 0;\n" ::: "memory");
        __syncthreads();

        if (i + 2 < NITER) stage(i + 2);

        const uint32_t sA_b = sbase + (uint32_t)(i % 3) * GSTAGE_B;
        const uint32_t sB_b = sA_b + GTILE_B;

#pragma unroll
        for (int ks = 0; ks < 4; ks++) {
            const uint32_t koff = (uint32_t)(ks * 32 + lm_kb);
            uint32_t a[2][4];
            ldsm_x4(a[0], sA_b + (uint32_t)((warp_m + lm_row) * 144) + koff);
            ldsm_x4(a[1], sA_b + (uint32_t)((warp_m + 16 + lm_row) * 144) + koff);
            uint32_t b[8][2];
#pragma unroll
            for (int g = 0; g < 4; g++) {
                uint32_t kf[4];
                ldsm_x4(kf, sB_b + (uint32_t)((warp_n + g * 16 + lm_row) * 144)
                            + koff);
                b[2 * g][0] = kf[0];     b[2 * g][1] = kf[2];
                b[2 * g + 1][0] = kf[1]; b[2 * g + 1][1] = kf[3];
            }
#pragma unroll
            for (int mt = 0; mt < 2; mt++)
#pragma unroll
                for (int nt = 0; nt < 8; nt++)
                    mma_f16(c[mt][nt], a[mt], b[nt]);
        }
    }

    const float* bb = bias;
    if (MODE == 3) {
        const int seg = (bx * 128) >> 10;
        bb = (seg == 0) ? bias : (seg == 1) ? bias2 : bias3;
    }

    const float inv_s2 = 0.70710678118654752f;
    __half* Ch = reinterpret_cast<__half*>(Cv);
    float* Cf = reinterpret_cast<float*>(Cv);
#pragma unroll
    for (int mt = 0; mt < 2; mt++) {
#pragma unroll
        for (int rh = 0; rh < 2; rh++) {
            const int m = by * 128 + warp_m + mt * 16 + lr + rh * 8;
#pragma unroll
            for (int nt = 0; nt < 8; nt++) {
                const int n = bx * 128 + warp_n + nt * 8 + 2 * lc;
                const int nb = (MODE == 3) ? (n & 1023) : n;
                float v0 = c[mt][nt][rh * 2 + 0] + bb[nb];
                float v1 = c[mt][nt][rh * 2 + 1] + bb[nb + 1];
                if (MODE == 1) {
                    v0 = 0.5f * v0 * (1.0f + erff(v0 * inv_s2));
                    v1 = 0.5f * v1 * (1.0f + erff(v1 * inv_s2));
                }
                if (MODE == 2) {
                    float2 rv = *reinterpret_cast<const float2*>(
                        Res + (size_t)m * N + n);
                    v0 += rv.x; v1 += rv.y;
                    *reinterpret_cast<float2*>(Cf + (size_t)m * N + n) =
                        make_float2(v0, v1);
                } else {
                    *reinterpret_cast<__half2*>(Ch + (size_t)m * N + n) =
                        __floats2half2_rn(v0, v1);
                }
            }
        }
    }
}

// ---------------------------------------------------------------------------
// fp16 flash attention (round-9/10 version, 3-buffer prefetch-first pipeline)
// ---------------------------------------------------------------------------
#define AQ_B 18432                // 128 x 144B Q tile
#define AKT_B 9216                // one 64 x 144B K or V tile
#define AKV_B (2 * AKT_B)         // K+V per buffer
#define ASMEM_B (AQ_B + 3 * AKV_B)   // 73728

__global__ __launch_bounds__(256, 2)
void attn_h_kernel(const __half* __restrict__ QKV,
                   __half* __restrict__ O)
{
    extern __shared__ char asmem[];

    const int bh = blockIdx.x;
    const int b  = bh / HH;
    const int h  = bh % HH;
    const int q0 = blockIdx.y * 128;
    const size_t baseq = (size_t)b * TT * QS + (size_t)h * HD;
    const size_t basek = baseq + DD;
    const size_t basev = baseq + 2 * DD;
    const size_t baseo = (size_t)b * TT * DD + (size_t)h * HD;

    const int tid = threadIdx.x;
    const int warp = tid >> 5, lane = tid & 31;
    const int lr = lane >> 2, lc = lane & 3;
    const int qr = warp * 16;

    const uint32_t sQ_b = smem_u32(asmem);
    const uint32_t sB0_b = sQ_b + AQ_B;

    const int lm_m   = lane >> 3;
    const int lm_row = (lm_m & 1) * 8 + (lane & 7);
    const int lm_kb  = (lm_m >> 1) * 16;

    const int st_r = tid >> 2;
    const int st_q = tid & 3;
    auto stage_tile = [&](uint32_t dstbase, const __half* gsrc) {
        const uint32_t d = dstbase + (uint32_t)(st_r * 144 + st_q * 32);
        const __half* g = gsrc + (size_t)st_r * QS + st_q * 16;
        cp_async16(d, g);
        cp_async16(d + 16, g + 8);
    };

    stage_tile(sQ_b,         QKV + baseq + (size_t)q0 * QS);
    stage_tile(sQ_b + AKT_B, QKV + baseq + (size_t)(q0 + 64) * QS);
    stage_tile(sB0_b,         QKV + basek);
    stage_tile(sB0_b + AKT_B, QKV + basev);
    CP_COMMIT();
    stage_tile(sB0_b + AKV_B,         QKV + basek + (size_t)64 * QS);
    stage_tile(sB0_b + AKV_B + AKT_B, QKV + basev + (size_t)64 * QS);
    CP_COMMIT();

    float m0 = -INFINITY, m1 = -INFINITY;
    float l0 = 0.0f, l1 = 0.0f;
    float o[8][4];
#pragma unroll
    for (int nt = 0; nt < 8; nt++)
#pragma unroll
        for (int j = 0; j < 4; j++) o[nt][j] = 0.0f;

    uint32_t qf[4][4];

    const int NT = TT / 64;
    for (int t = 0; t < NT; t++) {
        if (t < NT - 1)
            asm volatile("cp.async.wait_group 1;\n" ::: "memory");
        else
            asm volatile("cp.async.wait_group 0;\n" ::: "memory");
        __syncthreads();

        if (t + 2 < NT) {
            const uint32_t dst = sB0_b + (uint32_t)((t + 2) % 3) * AKV_B;
            stage_tile(dst,         QKV + basek + (size_t)((t + 2) * 64) * QS);
            stage_tile(dst + AKT_B, QKV + basev + (size_t)((t + 2) * 64) * QS);
            CP_COMMIT();
        }

        if (t == 0) {
#pragma unroll
            for (int ks = 0; ks < 4; ks++)
                ldsm_x4(qf[ks], sQ_b + (uint32_t)((qr + lm_row) * 144 +
                                                  ks * 32 + lm_kb));
        }

        const uint32_t sK_b = sB0_b + (uint32_t)(t % 3) * AKV_B;
        const uint32_t sV_b = sK_b + AKT_B;

        float s[8][4];
#pragma unroll
        for (int nt = 0; nt < 8; nt++)
#pragma unroll
            for (int j = 0; j < 4; j++) s[nt][j] = 0.0f;

#pragma unroll
        for (int ks = 0; ks < 4; ks++) {
#pragma unroll
            for (int g = 0; g < 4; g++) {
                uint32_t kf[4];
                ldsm_x4(kf, sK_b + (uint32_t)((g * 16 + lm_row) * 144 +
                                              ks * 32 + lm_kb));
                uint32_t b0[2] = {kf[0], kf[2]};
                uint32_t b1[2] = {kf[1], kf[3]};
                mma_f16(s[2 * g],     qf[ks], b0);
                mma_f16(s[2 * g + 1], qf[ks], b1);
            }
        }

        float mx0 = -INFINITY, mx1 = -INFINITY;
#pragma unroll
        for (int nt = 0; nt < 8; nt++) {
            s[nt][0] *= 0.125f; s[nt][1] *= 0.125f;
            s[nt][2] *= 0.125f; s[nt][3] *= 0.125f;
            mx0 = fmaxf(mx0, fmaxf(s[nt][0], s[nt][1]));
            mx1 = fmaxf(mx1, fmaxf(s[nt][2], s[nt][3]));
        }
        mx0 = fmaxf(mx0, __shfl_xor_sync(0xffffffffu, mx0, 1));
        mx0 = fmaxf(mx0, __shfl_xor_sync(0xffffffffu, mx0, 2));
        mx1 = fmaxf(mx1, __shfl_xor_sync(0xffffffffu, mx1, 1));
        mx1 = fmaxf(mx1, __shfl_xor_sync(0xffffffffu, mx1, 2));

        const float nm0 = fmaxf(m0, mx0), nm1 = fmaxf(m1, mx1);
        const float corr0 = __expf(m0 - nm0), corr1 = __expf(m1 - nm1);
        m0 = nm0; m1 = nm1;

        float ls0 = 0.0f, ls1 = 0.0f;
#pragma unroll
        for (int nt = 0; nt < 8; nt++) {
            s[nt][0] = __expf(s[nt][0] - nm0);
            s[nt][1] = __expf(s[nt][1] - nm0);
            s[nt][2] = __expf(s[nt][2] - nm1);
            s[nt][3] = __expf(s[nt][3] - nm1);
            ls0 += s[nt][0] + s[nt][1];
            ls1 += s[nt][2] + s[nt][3];
        }
        ls0 += __shfl_xor_sync(0xffffffffu, ls0, 1);
        ls0 += __shfl_xor_sync(0xffffffffu, ls0, 2);
        ls1 += __shfl_xor_sync(0xffffffffu, ls1, 1);
        ls1 += __shfl_xor_sync(0xffffffffu, ls1, 2);
        l0 = l0 * corr0 + ls0;
        l1 = l1 * corr1 + ls1;

#pragma unroll
        for (int nt = 0; nt < 8; nt++) {
            o[nt][0] *= corr0; o[nt][1] *= corr0;
            o[nt][2] *= corr1; o[nt][3] *= corr1;
        }

        const int key = (lane & 7) + ((lane >> 3) & 1) * 8;
#pragma unroll
        for (int ks = 0; ks < 4; ks++) {
            uint32_t pa[4];
            __half2 hh;
            hh = __floats2half2_rn(s[2 * ks][0], s[2 * ks][1]);
            pa[0] = *reinterpret_cast<uint32_t*>(&hh);
            hh = __floats2half2_rn(s[2 * ks][2], s[2 * ks][3]);
            pa[1] = *reinterpret_cast<uint32_t*>(&hh);
            hh = __floats2half2_rn(s[2 * ks + 1][0], s[2 * ks + 1][1]);
            pa[2] = *reinterpret_cast<uint32_t*>(&hh);
            hh = __floats2half2_rn(s[2 * ks + 1][2], s[2 * ks + 1][3]);
            pa[3] = *reinterpret_cast<uint32_t*>(&hh);

#pragma unroll
            for (int ntp = 0; ntp < 4; ntp++) {
                uint32_t r[4];
                const uint32_t addr = sV_b +
                    (uint32_t)((ks * 16 + key) * 144 + ntp * 32 +
                               ((lane >> 4) & 1) * 16);
                ldsm_x4_trans(r, addr);
                uint32_t b0[2] = {r[0], r[1]};
                uint32_t b1[2] = {r[2], r[3]};
                mma_f16(o[2 * ntp],     pa, b0);
                mma_f16(o[2 * ntp + 1], pa, b1);
            }
        }
    }

    const float inv0 = 1.0f / l0, inv1 = 1.0f / l1;
    const size_t row0 = baseo + (size_t)(q0 + qr + lr) * DD;
    const size_t row1 = baseo + (size_t)(q0 + qr + lr + 8) * DD;
#pragma unroll
    for (int nt = 0; nt < 8; nt++) {
        const int col = nt * 8 + 2 * lc;
        *reinterpret_cast<__half2*>(O + row0 + col) =
            __floats2half2_rn(o[nt][0] * inv0, o[nt][1] * inv0);
        *reinterpret_cast<__half2*>(O + row1 + col) =
            __floats2half2_rn(o[nt][2] * inv1, o[nt][3] * inv1);
    }
}

// ---------------------------------------------------------------------------
// Launch
// ---------------------------------------------------------------------------
template <typename T>
static T* symT(const void* symbol)
{
    void* p = nullptr;
    cudaGetSymbolAddress(&p, symbol);
    return reinterpret_cast<T*>(p);
}

extern "C" void kernel_launch(void* const* d_in, const int* in_sizes, int n_in,
                              void* d_out, int out_size)
{
    const float* x  = (const float*)d_in[0];
    const float* Wq = (const float*)d_in[1];  const float* bq = (const float*)d_in[2];
    const float* Wk = (const float*)d_in[3];  const float* bk = (const float*)d_in[4];
    const float* Wv = (const float*)d_in[5];  const float* bv = (const float*)d_in[6];
    const float* Wo = (const float*)d_in[7];  const float* bo = (const float*)d_in[8];
    const float* W1 = (const float*)d_in[9];  const float* b1 = (const float*)d_in[10];
    const float* W2 = (const float*)d_in[11]; const float* b2 = (const float*)d_in[12];
    const float* g1 = (const float*)d_in[13]; const float* be1 = (const float*)d_in[14];
    const float* g2 = (const float*)d_in[15]; const float* be2 = (const float*)d_in[16];
    float* out = (float*)d_out;

    float*  hln1  = symT<float>(g_hln1);
    __half* hln1t = symT<__half>(g_hln1t);
    __half* qkv   = symT<__half>(g_qkv);
    __half* ctx   = symT<__half>(g_ctx);
    float*  hb    = symT<float>(g_h);
    float*  h2b   = symT<float>(g_h2);
    __half* h2t   = symT<__half>(g_h2t);
    __half* ffb   = symT<__half>(g_ff);
    __half* Wqkv = symT<__half>(g_Wqkv);
    __half* WoT  = symT<__half>(g_WoT);
    __half* W1T  = symT<__half>(g_W1T);
    __half* W2T  = symT<__half>(g_W2T);

    cudaFuncSetAttribute(gemm_h<1>, cudaFuncAttributeMaxDynamicSharedMemorySize, GSMEM_B);
    cudaFuncSetAttribute(gemm_h<2>, cudaFuncAttributeMaxDynamicSharedMemorySize, GSMEM_B);
    cudaFuncSetAttribute(gemm_h<3>, cudaFuncAttributeMaxDynamicSharedMemorySize, GSMEM_B);
    cudaFuncSetAttribute(attn_h_kernel, cudaFuncAttributeMaxDynamicSharedMemorySize, ASMEM_B);

    // 0+1. fused prep: LN1 (8192 blocks) + all weight transposes (12288)
    prep_kernel<<<MROWS + 12288, 256>>>(
        x, g1, be1, hln1, hln1t,
        Wq, Wk, Wv, Wo, W1, W2, Wqkv, WoT, W1T, W2T);

    // 2. fused QKV projection -> packed [M][3072]
    {
        dim3 grid(QS / 128, MROWS / 128);
        gemm_h<3><<<grid, 256, GSMEM_B>>>(hln1t, Wqkv, bq, qkv, nullptr,
                                          bk, bv, MROWS, QS, DD);
    }

    // 3. attention (128 q-rows per block, 8 warps)
    {
        dim3 grid(BB * HH, TT / 128);
        attn_h_kernel<<<grid, 256, ASMEM_B>>>(qkv, ctx);
    }

    // 4. output projection + residual (fp32 out)
    {
        dim3 grid(DD / 128, MROWS / 128);
        gemm_h<2><<<grid, 256, GSMEM_B>>>(ctx, WoT, bo, hb, hln1,
                                          nullptr, nullptr, MROWS, DD, DD);
    }

    // 5. LN2
    ln_kernel<<<MROWS, 256>>>(hb, g2, be2, h2b, h2t);

    // 6. FFN up + exact GELU (half out, fp32 accum)
    {
        dim3 grid(FF / 128, MROWS / 128);
        gemm_h<1><<<grid, 256, GSMEM_B>>>(h2t, W1T, b1, ffb, nullptr,
                                          nullptr, nullptr, MROWS, FF, DD);
    }

    // 7. FFN down + bias + residual -> out (fp32)
    {
        dim3 grid(DD / 128, MROWS / 128);
        gemm_h<2><<<grid, 256, GSMEM_B>>>(ffb, W2T, b2, out, h2b,
                                          nullptr, nullptr, MROWS, DD, FF);
    }
}

// round 13
// speedup vs baseline: 1.0494x; 1.0035x over previous
#include <cuda_runtime.h>
#include <cuda_fp16.h>
#include <math.h>
#include <stdint.h>

// ---------------------------------------------------------------------------
// Problem constants
// ---------------------------------------------------------------------------
#define BB 8
#define TT 1024
#define DD 1024
#define HH 16
#define HD 64
#define FF 4096
#define MROWS (BB * TT)          // 8192
#define QS (3 * DD)              // packed QKV row stride
#define LN_EPS 1e-5f

// ---------------------------------------------------------------------------
// Scratch (__device__ globals; allocation-free rule)
// ---------------------------------------------------------------------------
__device__ float  g_hln1 [MROWS * DD];
__device__ __half g_hln1t[MROWS * DD];
__device__ __half g_qkv  [MROWS * QS];
__device__ __half g_ctx  [MROWS * DD];
__device__ float  g_h    [MROWS * DD];
__device__ float  g_h2   [MROWS * DD];
__device__ __half g_h2t  [MROWS * DD];
__device__ __half g_ff   [MROWS * FF];
__device__ __half g_Wqkv [3 * DD * DD];
__device__ __half g_WoT  [DD * DD];
__device__ __half g_W1T  [FF * DD];
__device__ __half g_W2T  [DD * FF];

// ---------------------------------------------------------------------------
// Helpers
// ---------------------------------------------------------------------------
__device__ __forceinline__ uint32_t smem_u32(const void* p) {
    uint32_t a;
    asm("{ .reg .u64 t; cvta.to.shared.u64 t, %1; cvt.u32.u64 %0, t; }"
        : "=r"(a) : "l"(p));
    return a;
}

__device__ __forceinline__ void cp_async16(uint32_t saddr, const void* gaddr) {
    asm volatile("cp.async.cg.shared.global [%0], [%1], 16;\n"
                 :: "r"(saddr), "l"(gaddr) : "memory");
}
#define CP_COMMIT() asm volatile("cp.async.commit_group;\n" ::: "memory")

__device__ __forceinline__ void mma_f16(float c[4], const uint32_t a[4],
                                        const uint32_t b[2]) {
    asm volatile(
        "mma.sync.aligned.m16n8k16.row.col.f32.f16.f16.f32 "
        "{%0,%1,%2,%3}, {%4,%5,%6,%7}, {%8,%9}, {%0,%1,%2,%3};"
        : "+f"(c[0]), "+f"(c[1]), "+f"(c[2]), "+f"(c[3])
        : "r"(a[0]), "r"(a[1]), "r"(a[2]), "r"(a[3]),
          "r"(b[0]), "r"(b[1]));
}

__device__ __forceinline__ void ldsm_x4(uint32_t r[4], uint32_t saddr) {
    asm volatile(
        "ldmatrix.sync.aligned.m8n8.x4.shared.b16 {%0,%1,%2,%3}, [%4];"
        : "=r"(r[0]), "=r"(r[1]), "=r"(r[2]), "=r"(r[3]) : "r"(saddr));
}

__device__ __forceinline__ void ldsm_x4_trans(uint32_t r[4], uint32_t saddr) {
    asm volatile(
        "ldmatrix.sync.aligned.m8n8.x4.trans.shared.b16 {%0,%1,%2,%3}, [%4];"
        : "=r"(r[0]), "=r"(r[1]), "=r"(r[2]), "=r"(r[3]) : "r"(saddr));
}

// ---------------------------------------------------------------------------
// Fused prep kernel: LN1 (blocks 0..8191) + ALL weight transposes
// ---------------------------------------------------------------------------
__global__ void prep_kernel(const float* __restrict__ x,
                            const float* __restrict__ gamma,
                            const float* __restrict__ beta,
                            float* __restrict__ dst,
                            __half* __restrict__ dsth,
                            const float* __restrict__ Wq,
                            const float* __restrict__ Wk,
                            const float* __restrict__ Wv,
                            const float* __restrict__ Wo,
                            const float* __restrict__ W1,
                            const float* __restrict__ W2,
                            __half* __restrict__ Wqkv,
                            __half* __restrict__ WoT,
                            __half* __restrict__ W1T,
                            __half* __restrict__ W2T)
{
    const int tid = threadIdx.x;

    if (blockIdx.x < MROWS) {
        const int row = blockIdx.x;
        const float4* in4 = reinterpret_cast<const float4*>(x + (size_t)row * DD);
        float4* out4 = reinterpret_cast<float4*>(dst + (size_t)row * DD);
        __half2* outh = reinterpret_cast<__half2*>(dsth + (size_t)row * DD);
        const float4* g4 = reinterpret_cast<const float4*>(gamma);
        const float4* b4 = reinterpret_cast<const float4*>(beta);

        float4 xv = in4[tid];
        float s  = xv.x + xv.y + xv.z + xv.w;
        float ss = xv.x * xv.x + xv.y * xv.y + xv.z * xv.z + xv.w * xv.w;
        for (int o = 16; o; o >>= 1) {
            s  += __shfl_xor_sync(0xffffffffu, s, o);
            ss += __shfl_xor_sync(0xffffffffu, ss, o);
        }
        __shared__ float rs[8], rss[8];
        __shared__ float smean, srstd;
        const int warp = tid >> 5, lane = tid & 31;
        if (lane == 0) { rs[warp] = s; rss[warp] = ss; }
        __syncthreads();
        if (warp == 0) {
            float a = (lane < 8) ? rs[lane] : 0.0f;
            float b = (lane < 8) ? rss[lane] : 0.0f;
            for (int o = 4; o; o >>= 1) {
                a += __shfl_xor_sync(0xffffffffu, a, o);
                b += __shfl_xor_sync(0xffffffffu, b, o);
            }
            if (lane == 0) {
                float mean = a * (1.0f / DD);
                float var  = (b - (float)DD * mean * mean) * (1.0f / (DD - 1));
                smean = mean;
                srstd = rsqrtf(var + LN_EPS);
            }
        }
        __syncthreads();
        const float mean = smean, rstd = srstd;
        float4 gv = g4[tid], bv = b4[tid];
        float4 o;
        o.x = (xv.x - mean) * rstd * gv.x + bv.x;
        o.y = (xv.y - mean) * rstd * gv.y + bv.y;
        o.z = (xv.z - mean) * rstd * gv.z + bv.z;
        o.w = (xv.w - mean) * rstd * gv.w + bv.w;
        out4[tid] = o;
        outh[2 * tid]     = __floats2half2_rn(o.x, o.y);
        outh[2 * tid + 1] = __floats2half2_rn(o.z, o.w);
    } else {
        __shared__ float t[32][33];
        const int tblk = blockIdx.x - MROWS;
        const int tx = tid & 31, ty = tid >> 5;

        const float* in; __half* out; int K, N, local;
        if (tblk < 3072) {
            const int seg = tblk >> 10;
            in  = (seg == 0) ? Wq : (seg == 1) ? Wk : Wv;
            out = Wqkv + (size_t)seg * DD * DD;
            K = DD; N = DD; local = tblk & 1023;
        } else if (tblk < 4096) {
            in = Wo; out = WoT; K = DD; N = DD; local = tblk - 3072;
        } else if (tblk < 8192) {
            in = W1; out = W1T; K = DD; N = FF; local = tblk - 4096;
        } else {
            in = W2; out = W2T; K = FF; N = DD; local = tblk - 8192;
        }
        const int ntn = N >> 5;
        const int n0 = (local % ntn) * 32;
        const int k0 = (local / ntn) * 32;

        for (int i = ty; i < 32; i += 8)
            t[i][tx] = in[(size_t)(k0 + i) * N + n0 + tx];
        __syncthreads();
        for (int i = ty; i < 32; i += 8)
            out[(size_t)(n0 + i) * K + k0 + tx] = __float2half_rn(t[tx][i]);
    }
}

// ---------------------------------------------------------------------------
// LayerNorm (unbiased var, ddof=1), dual output: fp32 + half   (LN2)
// ---------------------------------------------------------------------------
__global__ void ln_kernel(const float* __restrict__ src,
                          const float* __restrict__ gamma,
                          const float* __restrict__ beta,
                          float* __restrict__ dst,
                          __half* __restrict__ dsth)
{
    const int row = blockIdx.x;
    const int tid = threadIdx.x;
    const float4* in4 = reinterpret_cast<const float4*>(src + (size_t)row * DD);
    float4* out4 = reinterpret_cast<float4*>(dst + (size_t)row * DD);
    __half2* outh = reinterpret_cast<__half2*>(dsth + (size_t)row * DD);
    const float4* g4 = reinterpret_cast<const float4*>(gamma);
    const float4* b4 = reinterpret_cast<const float4*>(beta);

    float4 x = in4[tid];
    float s  = x.x + x.y + x.z + x.w;
    float ss = x.x * x.x + x.y * x.y + x.z * x.z + x.w * x.w;
    for (int o = 16; o; o >>= 1) {
        s  += __shfl_xor_sync(0xffffffffu, s, o);
        ss += __shfl_xor_sync(0xffffffffu, ss, o);
    }
    __shared__ float rs[8], rss[8];
    __shared__ float smean, srstd;
    const int warp = tid >> 5, lane = tid & 31;
    if (lane == 0) { rs[warp] = s; rss[warp] = ss; }
    __syncthreads();
    if (warp == 0) {
        float a = (lane < 8) ? rs[lane] : 0.0f;
        float b = (lane < 8) ? rss[lane] : 0.0f;
        for (int o = 4; o; o >>= 1) {
            a += __shfl_xor_sync(0xffffffffu, a, o);
            b += __shfl_xor_sync(0xffffffffu, b, o);
        }
        if (lane == 0) {
            float mean = a * (1.0f / DD);
            float var  = (b - (float)DD * mean * mean) * (1.0f / (DD - 1));
            smean = mean;
            srstd = rsqrtf(var + LN_EPS);
        }
    }
    __syncthreads();
    const float mean = smean, rstd = srstd;
    float4 gv = g4[tid], bv = b4[tid];
    float4 o;
    o.x = (x.x - mean) * rstd * gv.x + bv.x;
    o.y = (x.y - mean) * rstd * gv.y + bv.y;
    o.z = (x.z - mean) * rstd * gv.z + bv.z;
    o.w = (x.w - mean) * rstd * gv.w + bv.w;
    out4[tid] = o;
    outh[2 * tid]     = __floats2half2_rn(o.x, o.y);
    outh[2 * tid + 1] = __floats2half2_rn(o.z, o.w);
}

// ---------------------------------------------------------------------------
// fp16 mma GEMM v2: M64 x N128 tile, 256 threads (8 warps as 2m x 4n,
// warp tile 32x32), 2-stage cp.async, ldmatrix frags, 3 CTAs/SM.
// C[M,N] = A[M,K] @ B^T (B [N,K] K-major, half) + bias
// MODE 1: half out, gelu(acc+bias)   MODE 2: float out, acc+bias+Res
// MODE 3: half out, segmented bias (QKV)
// ---------------------------------------------------------------------------
#define ATILE_B (64 * 144)              // 9216
#define BTILE_B (128 * 144)             // 18432
#define GSTAGE_B (ATILE_B + BTILE_B)    // 27648
#define GSMEM_B (2 * GSTAGE_B)          // 55296

template <int MODE>
__global__ __launch_bounds__(256, 3)
void gemm_h(const __half* __restrict__ A, const __half* __restrict__ B,
            const float* __restrict__ bias, void* __restrict__ Cv,
            const float* __restrict__ Res,
            const float* __restrict__ bias2, const float* __restrict__ bias3,
            int M, int N, int K)
{
    extern __shared__ char dynsmem[];
    const int tid = threadIdx.x;
    const int wid = tid >> 5, lane = tid & 31;
    const int bx = blockIdx.x, by = blockIdx.y;

    const int warp_m = (wid & 1) * 32;        // 2 m-warps
    const int warp_n = (wid >> 1) * 32;       // 4 n-warps
    const int lr = lane >> 2;
    const int lc = lane & 3;

    const int lm_m   = lane >> 3;
    const int lm_row = (lm_m & 1) * 8 + (lane & 7);
    const int lm_kb  = (lm_m >> 1) * 16;

    const uint32_t sbase = smem_u32(dynsmem);

    // A staging: 64 rows, thread -> (row = tid/4, quarter = tid%4), 32B each
    const int a_r = tid >> 2;
    const int a_q = tid & 3;
    const __half* gA = A + (size_t)(by * 64 + a_r) * K + a_q * 16;
    const uint32_t a_off = (uint32_t)(a_r * 144 + a_q * 32);
    // B staging: 128 rows, thread -> (row = tid/2, half = tid%2), 64B each
    const int b_r = tid >> 1;
    const int b_h = tid & 1;
    const __half* gB = B + (size_t)(bx * 128 + b_r) * K + b_h * 32;
    const uint32_t b_off = (uint32_t)(b_r * 144 + b_h * 64);

    const int NITER = K >> 6;

    auto stage = [&](int s) {
        const uint32_t base = sbase + (uint32_t)(s & 1) * GSTAGE_B;
        const int k0 = s << 6;
        cp_async16(base + a_off,      gA + k0);
        cp_async16(base + a_off + 16, gA + k0 + 8);
#pragma unroll
        for (int p = 0; p < 4; p++)
            cp_async16(base + ATILE_B + b_off + p * 16, gB + k0 + p * 8);
        CP_COMMIT();
    };

    float c[2][4][4];
#pragma unroll
    for (int mt = 0; mt < 2; mt++)
#pragma unroll
        for (int nt = 0; nt < 4; nt++)
#pragma unroll
            for (int r = 0; r < 4; r++) c[mt][nt][r] = 0.0f;

    stage(0);
    if (NITER > 1) stage(1);

    for (int i = 0; i < NITER; i++) {
        if (i < NITER - 1)
            asm volatile("cp.async.wait_group 1;\n" ::: "memory");
        else
            asm volatile("cp.async.wait_group 0;\n" ::: "memory");
        __syncthreads();

        const uint32_t sA_b = sbase + (uint32_t)(i & 1) * GSTAGE_B;
        const uint32_t sB_b = sA_b + ATILE_B;

#pragma unroll
        for (int ks = 0; ks < 4; ks++) {
            const uint32_t koff = (uint32_t)(ks * 32 + lm_kb);
            uint32_t a[2][4];
            ldsm_x4(a[0], sA_b + (uint32_t)((lm_row) * 144) + koff);
            ldsm_x4(a[1], sA_b + (uint32_t)((32 + lm_row) * 144) + koff);
            uint32_t b[4][2];
#pragma unroll
            for (int g = 0; g < 2; g++) {
                uint32_t kf[4];
                ldsm_x4(kf, sB_b + (uint32_t)((warp_n + g * 16 + lm_row) * 144)
                            + koff);
                b[2 * g][0] = kf[0];     b[2 * g][1] = kf[2];
                b[2 * g + 1][0] = kf[1]; b[2 * g + 1][1] = kf[3];
            }
            // warp_m selects which a frag this warp uses per mt
#pragma unroll
            for (int mt = 0; mt < 2; mt++) {
                const int am = (warp_m >> 5) * 0 + mt;   // mt within warp tile
                // warp tile rows: warp_m + mt*16 -> a index (warp_m+mt*16)/16
                const int ai = (warp_m + mt * 16) >> 4;
#pragma unroll
                for (int nt = 0; nt < 4; nt++)
                    mma_f16(c[mt][nt], a[ai >> 1 == 0 ? ai & 1 : ai & 1], b[nt]);
                (void)am;
            }
        }
    }

    const float* bb = bias;
    if (MODE == 3) {
        const int seg = (bx * 128) >> 10;
        bb = (seg == 0) ? bias : (seg == 1) ? bias2 : bias3;
    }

    const float inv_s2 = 0.70710678118654752f;
    __half* Ch = reinterpret_cast<__half*>(Cv);
    float* Cf = reinterpret_cast<float*>(Cv);
#pragma unroll
    for (int mt = 0; mt < 2; mt++) {
#pragma unroll
        for (int rh = 0; rh < 2; rh++) {
            const int m = by * 64 + warp_m + mt * 16 + lr + rh * 8;
#pragma unroll
            for (int nt = 0; nt < 4; nt++) {
                const int n = bx * 128 + warp_n + nt * 8 + 2 * lc;
                const int nb = (MODE == 3) ? (n & 1023) : n;
                float v0 = c[mt][nt][rh * 2 + 0] + bb[nb];
                float v1 = c[mt][nt][rh * 2 + 1] + bb[nb + 1];
                if (MODE == 1) {
                    v0 = 0.5f * v0 * (1.0f + erff(v0 * inv_s2));
                    v1 = 0.5f * v1 * (1.0f + erff(v1 * inv_s2));
                }
                if (MODE == 2) {
                    float2 rv = *reinterpret_cast<const float2*>(
                        Res + (size_t)m * N + n);
                    v0 += rv.x; v1 += rv.y;
                    *reinterpret_cast<float2*>(Cf + (size_t)m * N + n) =
                        make_float2(v0, v1);
                } else {
                    *reinterpret_cast<__half2*>(Ch + (size_t)m * N + n) =
                        __floats2half2_rn(v0, v1);
                }
            }
        }
    }

    // prefetch for next iteration happens implicitly via loop structure:
    // (2-stage: stage(i+1) was issued before loop or in previous iteration)
}

// NOTE on pipeline: with 2 stages we must re-stage inside the loop. The loop
// above lacks it; correct version below via macro trick is avoided — instead
// the loop is rewritten here as a second definition guard. (See launch side:
// we use gemm_h2 which includes the re-stage.)

// ---------------------------------------------------------------------------
// fp16 flash attention (round-9/10 version, 3-buffer prefetch-first pipeline)
// ---------------------------------------------------------------------------
#define AQ_B 18432
#define AKT_B 9216
#define AKV_B (2 * AKT_B)
#define ASMEM_B (AQ_B + 3 * AKV_B)

__global__ __launch_bounds__(256, 2)
void attn_h_kernel(const __half* __restrict__ QKV,
                   __half* __restrict__ O)
{
    extern __shared__ char asmem[];

    const int bh = blockIdx.x;
    const int b  = bh / HH;
    const int h  = bh % HH;
    const int q0 = blockIdx.y * 128;
    const size_t baseq = (size_t)b * TT * QS + (size_t)h * HD;
    const size_t basek = baseq + DD;
    const size_t basev = baseq + 2 * DD;
    const size_t baseo = (size_t)b * TT * DD + (size_t)h * HD;

    const int tid = threadIdx.x;
    const int warp = tid >> 5, lane = tid & 31;
    const int lr = lane >> 2, lc = lane & 3;
    const int qr = warp * 16;

    const uint32_t sQ_b = smem_u32(asmem);
    const uint32_t sB0_b = sQ_b + AQ_B;

    const int lm_m   = lane >> 3;
    const int lm_row = (lm_m & 1) * 8 + (lane & 7);
    const int lm_kb  = (lm_m >> 1) * 16;

    const int st_r = tid >> 2;
    const int st_q = tid & 3;
    auto stage_tile = [&](uint32_t dstbase, const __half* gsrc) {
        const uint32_t d = dstbase + (uint32_t)(st_r * 144 + st_q * 32);
        const __half* g = gsrc + (size_t)st_r * QS + st_q * 16;
        cp_async16(d, g);
        cp_async16(d + 16, g + 8);
    };

    stage_tile(sQ_b,         QKV + baseq + (size_t)q0 * QS);
    stage_tile(sQ_b + AKT_B, QKV + baseq + (size_t)(q0 + 64) * QS);
    stage_tile(sB0_b,         QKV + basek);
    stage_tile(sB0_b + AKT_B, QKV + basev);
    CP_COMMIT();
    stage_tile(sB0_b + AKV_B,         QKV + basek + (size_t)64 * QS);
    stage_tile(sB0_b + AKV_B + AKT_B, QKV + basev + (size_t)64 * QS);
    CP_COMMIT();

    float m0 = -INFINITY, m1 = -INFINITY;
    float l0 = 0.0f, l1 = 0.0f;
    float o[8][4];
#pragma unroll
    for (int nt = 0; nt < 8; nt++)
#pragma unroll
        for (int j = 0; j < 4; j++) o[nt][j] = 0.0f;

    uint32_t qf[4][4];

    const int NT = TT / 64;
    for (int t = 0; t < NT; t++) {
        if (t < NT - 1)
            asm volatile("cp.async.wait_group 1;\n" ::: "memory");
        else
            asm volatile("cp.async.wait_group 0;\n" ::: "memory");
        __syncthreads();

        if (t + 2 < NT) {
            const uint32_t dst = sB0_b + (uint32_t)((t + 2) % 3) * AKV_B;
            stage_tile(dst,         QKV + basek + (size_t)((t + 2) * 64) * QS);
            stage_tile(dst + AKT_B, QKV + basev + (size_t)((t + 2) * 64) * QS);
            CP_COMMIT();
        }

        if (t == 0) {
#pragma unroll
            for (int ks = 0; ks < 4; ks++)
                ldsm_x4(qf[ks], sQ_b + (uint32_t)((qr + lm_row) * 144 +
                                                  ks * 32 + lm_kb));
        }

        const uint32_t sK_b = sB0_b + (uint32_t)(t % 3) * AKV_B;
        const uint32_t sV_b = sK_b + AKT_B;

        float s[8][4];
#pragma unroll
        for (int nt = 0; nt < 8; nt++)
#pragma unroll
            for (int j = 0; j < 4; j++) s[nt][j] = 0.0f;

#pragma unroll
        for (int ks = 0; ks < 4; ks++) {
#pragma unroll
            for (int g = 0; g < 4; g++) {
                uint32_t kf[4];
                ldsm_x4(kf, sK_b + (uint32_t)((g * 16 + lm_row) * 144 +
                                              ks * 32 + lm_kb));
                uint32_t b0[2] = {kf[0], kf[2]};
                uint32_t b1[2] = {kf[1], kf[3]};
                mma_f16(s[2 * g],     qf[ks], b0);
                mma_f16(s[2 * g + 1], qf[ks], b1);
            }
        }

        float mx0 = -INFINITY, mx1 = -INFINITY;
#pragma unroll
        for (int nt = 0; nt < 8; nt++) {
            s[nt][0] *= 0.125f; s[nt][1] *= 0.125f;
            s[nt][2] *= 0.125f; s[nt][3] *= 0.125f;
            mx0 = fmaxf(mx0, fmaxf(s[nt][0], s[nt][1]));
            mx1 = fmaxf(mx1, fmaxf(s[nt][2], s[nt][3]));
        }
        mx0 = fmaxf(mx0, __shfl_xor_sync(0xffffffffu, mx0, 1));
        mx0 = fmaxf(mx0, __shfl_xor_sync(0xffffffffu, mx0, 2));
        mx1 = fmaxf(mx1, __shfl_xor_sync(0xffffffffu, mx1, 1));
        mx1 = fmaxf(mx1, __shfl_xor_sync(0xffffffffu, mx1, 2));

        const float nm0 = fmaxf(m0, mx0), nm1 = fmaxf(m1, mx1);
        const float corr0 = __expf(m0 - nm0), corr1 = __expf(m1 - nm1);
        m0 = nm0; m1 = nm1;

        float ls0 = 0.0f, ls1 = 0.0f;
#pragma unroll
        for (int nt = 0; nt < 8; nt++) {
            s[nt][0] = __expf(s[nt][0] - nm0);
            s[nt][1] = __expf(s[nt][1] - nm0);
            s[nt][2] = __expf(s[nt][2] - nm1);
            s[nt][3] = __expf(s[nt][3] - nm1);
            ls0 += s[nt][0] + s[nt][1];
            ls1 += s[nt][2] + s[nt][3];
        }
        ls0 += __shfl_xor_sync(0xffffffffu, ls0, 1);
        ls0 += __shfl_xor_sync(0xffffffffu, ls0, 2);
        ls1 += __shfl_xor_sync(0xffffffffu, ls1, 1);
        ls1 += __shfl_xor_sync(0xffffffffu, ls1, 2);
        l0 = l0 * corr0 + ls0;
        l1 = l1 * corr1 + ls1;

#pragma unroll
        for (int nt = 0; nt < 8; nt++) {
            o[nt][0] *= corr0; o[nt][1] *= corr0;
            o[nt][2] *= corr1; o[nt][3] *= corr1;
        }

        const int key = (lane & 7) + ((lane >> 3) & 1) * 8;
#pragma unroll
        for (int ks = 0; ks < 4; ks++) {
            uint32_t pa[4];
            __half2 hh;
            hh = __floats2half2_rn(s[2 * ks][0], s[2 * ks][1]);
            pa[0] = *reinterpret_cast<uint32_t*>(&hh);
            hh = __floats2half2_rn(s[2 * ks][2], s[2 * ks][3]);
            pa[1] = *reinterpret_cast<uint32_t*>(&hh);
            hh = __floats2half2_rn(s[2 * ks + 1][0], s[2 * ks + 1][1]);
            pa[2] = *reinterpret_cast<uint32_t*>(&hh);
            hh = __floats2half2_rn(s[2 * ks + 1][2], s[2 * ks + 1][3]);
            pa[3] = *reinterpret_cast<uint32_t*>(&hh);

#pragma unroll
            for (int ntp = 0; ntp < 4; ntp++) {
                uint32_t r[4];
                const uint32_t addr = sV_b +
                    (uint32_t)((ks * 16 + key) * 144 + ntp * 32 +
                               ((lane >> 4) & 1) * 16);
                ldsm_x4_trans(r, addr);
                uint32_t b0[2] = {r[0], r[1]};
                uint32_t b1[2] = {r[2], r[3]};
                mma_f16(o[2 * ntp],     pa, b0);
                mma_f16(o[2 * ntp + 1], pa, b1);
            }
        }
    }

    const float inv0 = 1.0f / l0, inv1 = 1.0f / l1;
    const size_t row0 = baseo + (size_t)(q0 + qr + lr) * DD;
    const size_t row1 = baseo + (size_t)(q0 + qr + lr + 8) * DD;
#pragma unroll
    for (int nt = 0; nt < 8; nt++) {
        const int col = nt * 8 + 2 * lc;
        *reinterpret_cast<__half2*>(O + row0 + col) =
            __floats2half2_rn(o[nt][0] * inv0, o[nt][1] * inv0);
        *reinterpret_cast<__half2*>(O + row1 + col) =
            __floats2half2_rn(o[nt][2] * inv1, o[nt][3] * inv1);
    }
}

// ---------------------------------------------------------------------------
// gemm_h corrected: the loop above omitted the in-loop re-stage for 2-stage
// pipelining. Define the real kernel used at launch.
// ---------------------------------------------------------------------------
template <int MODE>
__global__ __launch_bounds__(256, 3)
void gemm_h2(const __half* __restrict__ A, const __half* __restrict__ B,
             const float* __restrict__ bias, void* __restrict__ Cv,
             const float* __restrict__ Res,
             const float* __restrict__ bias2, const float* __restrict__ bias3,
             int M, int N, int K)
{
    extern __shared__ char dynsmem[];
    const int tid = threadIdx.x;
    const int wid = tid >> 5, lane = tid & 31;
    const int bx = blockIdx.x, by = blockIdx.y;

    const int warp_m = (wid & 1) * 32;
    const int warp_n = (wid >> 1) * 32;
    const int lr = lane >> 2;
    const int lc = lane & 3;

    const int lm_m   = lane >> 3;
    const int lm_row = (lm_m & 1) * 8 + (lane & 7);
    const int lm_kb  = (lm_m >> 1) * 16;

    const uint32_t sbase = smem_u32(dynsmem);

    const int a_r = tid >> 2;
    const int a_q = tid & 3;
    const __half* gA = A + (size_t)(by * 64 + a_r) * K + a_q * 16;
    const uint32_t a_off = (uint32_t)(a_r * 144 + a_q * 32);
    const int b_r = tid >> 1;
    const int b_h = tid & 1;
    const __half* gB = B + (size_t)(bx * 128 + b_r) * K + b_h * 32;
    const uint32_t b_off = (uint32_t)(b_r * 144 + b_h * 64);

    const int NITER = K >> 6;

    auto stage = [&](int s) {
        const uint32_t base = sbase + (uint32_t)(s & 1) * GSTAGE_B;
        const int k0 = s << 6;
        cp_async16(base + a_off,      gA + k0);
        cp_async16(base + a_off + 16, gA + k0 + 8);
#pragma unroll
        for (int p = 0; p < 4; p++)
            cp_async16(base + ATILE_B + b_off + p * 16, gB + k0 + p * 8);
        CP_COMMIT();
    };

    float c[2][4][4];
#pragma unroll
    for (int mt = 0; mt < 2; mt++)
#pragma unroll
        for (int nt = 0; nt < 4; nt++)
#pragma unroll
            for (int r = 0; r < 4; r++) c[mt][nt][r] = 0.0f;

    stage(0);
    if (NITER > 1) stage(1);

    for (int i = 0; i < NITER; i++) {
        if (i < NITER - 1)
            asm volatile("cp.async.wait_group 1;\n" ::: "memory");
        else
            asm volatile("cp.async.wait_group 0;\n" ::: "memory");
        __syncthreads();

        const uint32_t sA_b = sbase + (uint32_t)(i & 1) * GSTAGE_B;
        const uint32_t sB_b = sA_b + ATILE_B;

        // warp tile rows: warp_m..warp_m+31 -> two 16-row A frag groups
#pragma unroll
        for (int ks = 0; ks < 4; ks++) {
            const uint32_t koff = (uint32_t)(ks * 32 + lm_kb);
            uint32_t a[2][4];
            ldsm_x4(a[0], sA_b + (uint32_t)((warp_m + lm_row) * 144) + koff);
            ldsm_x4(a[1], sA_b + (uint32_t)((warp_m + 16 + lm_row) * 144) + koff);
            uint32_t b[4][2];
#pragma unroll
            for (int g = 0; g < 2; g++) {
                uint32_t kf[4];
                ldsm_x4(kf, sB_b + (uint32_t)((warp_n + g * 16 + lm_row) * 144)
                            + koff);
                b[2 * g][0] = kf[0];     b[2 * g][1] = kf[2];
                b[2 * g + 1][0] = kf[1]; b[2 * g + 1][1] = kf[3];
            }
#pragma unroll
            for (int mt = 0; mt < 2; mt++)
#pragma unroll
                for (int nt = 0; nt < 4; nt++)
                    mma_f16(c[mt][nt], a[mt], b[nt]);
        }

        __syncthreads();
        if (i + 2 < NITER) stage(i + 2);
    }

    const float* bb = bias;
    if (MODE == 3) {
        const int seg = (bx * 128) >> 10;
        bb = (seg == 0) ? bias : (seg == 1) ? bias2 : bias3;
    }

    const float inv_s2 = 0.70710678118654752f;
    __half* Ch = reinterpret_cast<__half*>(Cv);
    float* Cf = reinterpret_cast<float*>(Cv);
#pragma unroll
    for (int mt = 0; mt < 2; mt++) {
#pragma unroll
        for (int rh = 0; rh < 2; rh++) {
            const int m = by * 64 + warp_m + mt * 16 + lr + rh * 8;
#pragma unroll
            for (int nt = 0; nt < 4; nt++) {
                const int n = bx * 128 + warp_n + nt * 8 + 2 * lc;
                const int nb = (MODE == 3) ? (n & 1023) : n;
                float v0 = c[mt][nt][rh * 2 + 0] + bb[nb];
                float v1 = c[mt][nt][rh * 2 + 1] + bb[nb + 1];
                if (MODE == 1) {
                    v0 = 0.5f * v0 * (1.0f + erff(v0 * inv_s2));
                    v1 = 0.5f * v1 * (1.0f + erff(v1 * inv_s2));
                }
                if (MODE == 2) {
                    float2 rv = *reinterpret_cast<const float2*>(
                        Res + (size_t)m * N + n);
                    v0 += rv.x; v1 += rv.y;
                    *reinterpret_cast<float2*>(Cf + (size_t)m * N + n) =
                        make_float2(v0, v1);
                } else {
                    *reinterpret_cast<__half2*>(Ch + (size_t)m * N + n) =
                        __floats2half2_rn(v0, v1);
                }
            }
        }
    }
}

// ---------------------------------------------------------------------------
// Launch
// ---------------------------------------------------------------------------
template <typename T>
static T* symT(const void* symbol)
{
    void* p = nullptr;
    cudaGetSymbolAddress(&p, symbol);
    return reinterpret_cast<T*>(p);
}

extern "C" void kernel_launch(void* const* d_in, const int* in_sizes, int n_in,
                              void* d_out, int out_size)
{
    const float* x  = (const float*)d_in[0];
    const float* Wq = (const float*)d_in[1];  const float* bq = (const float*)d_in[2];
    const float* Wk = (const float*)d_in[3];  const float* bk = (const float*)d_in[4];
    const float* Wv = (const float*)d_in[5];  const float* bv = (const float*)d_in[6];
    const float* Wo = (const float*)d_in[7];  const float* bo = (const float*)d_in[8];
    const float* W1 = (const float*)d_in[9];  const float* b1 = (const float*)d_in[10];
    const float* W2 = (const float*)d_in[11]; const float* b2 = (const float*)d_in[12];
    const float* g1 = (const float*)d_in[13]; const float* be1 = (const float*)d_in[14];
    const float* g2 = (const float*)d_in[15]; const float* be2 = (const float*)d_in[16];
    float* out = (float*)d_out;

    float*  hln1  = symT<float>(g_hln1);
    __half* hln1t = symT<__half>(g_hln1t);
    __half* qkv   = symT<__half>(g_qkv);
    __half* ctx   = symT<__half>(g_ctx);
    float*  hb    = symT<float>(g_h);
    float*  h2b   = symT<float>(g_h2);
    __half* h2t   = symT<__half>(g_h2t);
    __half* ffb   = symT<__half>(g_ff);
    __half* Wqkv = symT<__half>(g_Wqkv);
    __half* WoT  = symT<__half>(g_WoT);
    __half* W1T  = symT<__half>(g_W1T);
    __half* W2T  = symT<__half>(g_W2T);

    cudaFuncSetAttribute(gemm_h2<1>, cudaFuncAttributeMaxDynamicSharedMemorySize, GSMEM_B);
    cudaFuncSetAttribute(gemm_h2<2>, cudaFuncAttributeMaxDynamicSharedMemorySize, GSMEM_B);
    cudaFuncSetAttribute(gemm_h2<3>, cudaFuncAttributeMaxDynamicSharedMemorySize, GSMEM_B);
    cudaFuncSetAttribute(attn_h_kernel, cudaFuncAttributeMaxDynamicSharedMemorySize, ASMEM_B);

    // 0+1. fused prep: LN1 + all weight transposes
    prep_kernel<<<MROWS + 12288, 256>>>(
        x, g1, be1, hln1, hln1t,
        Wq, Wk, Wv, Wo, W1, W2, Wqkv, WoT, W1T, W2T);

    // 2. fused QKV projection -> packed [M][3072]
    {
        dim3 grid(QS / 128, MROWS / 64);
        gemm_h2<3><<<grid, 256, GSMEM_B>>>(hln1t, Wqkv, bq, qkv, nullptr,
                                           bk, bv, MROWS, QS, DD);
    }

    // 3. attention (128 q-rows per block, 8 warps)
    {
        dim3 grid(BB * HH, TT / 128);
        attn_h_kernel<<<grid, 256, ASMEM_B>>>(qkv, ctx);
    }

    // 4. output projection + residual (fp32 out)
    {
        dim3 grid(DD / 128, MROWS / 64);
        gemm_h2<2><<<grid, 256, GSMEM_B>>>(ctx, WoT, bo, hb, hln1,
                                           nullptr, nullptr, MROWS, DD, DD);
    }

    // 5. LN2
    ln_kernel<<<MROWS, 256>>>(hb, g2, be2, h2b, h2t);

    // 6. FFN up + exact GELU (half out)
    {
        dim3 grid(FF / 128, MROWS / 64);
        gemm_h2<1><<<grid, 256, GSMEM_B>>>(h2t, W1T, b1, ffb, nullptr,
                                           nullptr, nullptr, MROWS, FF, DD);
    }

    // 7. FFN down + bias + residual -> out (fp32)
    {
        dim3 grid(DD / 128, MROWS / 64);
        gemm_h2<2><<<grid, 256, GSMEM_B>>>(ffb, W2T, b2, out, h2b,
                                           nullptr, nullptr, MROWS, DD, FF);
    }
}

// round 14
// speedup vs baseline: 1.1971x; 1.1408x over previous
#include <cuda_runtime.h>
#include <cuda_fp16.h>
#include <math.h>
#include <stdint.h>

// ---------------------------------------------------------------------------
// Problem constants
// ---------------------------------------------------------------------------
#define BB 8
#define TT 1024
#define DD 1024
#define HH 16
#define HD 64
#define FF 4096
#define MROWS (BB * TT)          // 8192
#define QS (3 * DD)              // packed QKV row stride
#define LN_EPS 1e-5f

// ---------------------------------------------------------------------------
// Scratch (__device__ globals; allocation-free rule)
// ---------------------------------------------------------------------------
__device__ float  g_hln1 [MROWS * DD];
__device__ __half g_hln1t[MROWS * DD];
__device__ __half g_qkv  [MROWS * QS];
__device__ __half g_ctx  [MROWS * DD];
__device__ float  g_h    [MROWS * DD];
__device__ float  g_h2   [MROWS * DD];
__device__ __half g_h2t  [MROWS * DD];
__device__ __half g_ff   [MROWS * FF];
__device__ __half g_Wqkv [3 * DD * DD];
__device__ __half g_WoT  [DD * DD];
__device__ __half g_W1T  [FF * DD];
__device__ __half g_W2T  [DD * FF];

// ---------------------------------------------------------------------------
// Helpers
// ---------------------------------------------------------------------------
__device__ __forceinline__ uint32_t smem_u32(const void* p) {
    uint32_t a;
    asm("{ .reg .u64 t; cvta.to.shared.u64 t, %1; cvt.u32.u64 %0, t; }"
        : "=r"(a) : "l"(p));
    return a;
}

__device__ __forceinline__ void cp_async16(uint32_t saddr, const void* gaddr) {
    asm volatile("cp.async.cg.shared.global [%0], [%1], 16;\n"
                 :: "r"(saddr), "l"(gaddr) : "memory");
}
#define CP_COMMIT() asm volatile("cp.async.commit_group;\n" ::: "memory")

__device__ __forceinline__ void mma_f16(float c[4], const uint32_t a[4],
                                        const uint32_t b[2]) {
    asm volatile(
        "mma.sync.aligned.m16n8k16.row.col.f32.f16.f16.f32 "
        "{%0,%1,%2,%3}, {%4,%5,%6,%7}, {%8,%9}, {%0,%1,%2,%3};"
        : "+f"(c[0]), "+f"(c[1]), "+f"(c[2]), "+f"(c[3])
        : "r"(a[0]), "r"(a[1]), "r"(a[2]), "r"(a[3]),
          "r"(b[0]), "r"(b[1]));
}

__device__ __forceinline__ void ldsm_x4(uint32_t r[4], uint32_t saddr) {
    asm volatile(
        "ldmatrix.sync.aligned.m8n8.x4.shared.b16 {%0,%1,%2,%3}, [%4];"
        : "=r"(r[0]), "=r"(r[1]), "=r"(r[2]), "=r"(r[3]) : "r"(saddr));
}

__device__ __forceinline__ void ldsm_x4_trans(uint32_t r[4], uint32_t saddr) {
    asm volatile(
        "ldmatrix.sync.aligned.m8n8.x4.trans.shared.b16 {%0,%1,%2,%3}, [%4];"
        : "=r"(r[0]), "=r"(r[1]), "=r"(r[2]), "=r"(r[3]) : "r"(saddr));
}

// ---------------------------------------------------------------------------
// Fused prep kernel: LN1 (blocks 0..8191) + ALL weight transposes
// ---------------------------------------------------------------------------
__global__ void prep_kernel(const float* __restrict__ x,
                            const float* __restrict__ gamma,
                            const float* __restrict__ beta,
                            float* __restrict__ dst,
                            __half* __restrict__ dsth,
                            const float* __restrict__ Wq,
                            const float* __restrict__ Wk,
                            const float* __restrict__ Wv,
                            const float* __restrict__ Wo,
                            const float* __restrict__ W1,
                            const float* __restrict__ W2,
                            __half* __restrict__ Wqkv,
                            __half* __restrict__ WoT,
                            __half* __restrict__ W1T,
                            __half* __restrict__ W2T)
{
    const int tid = threadIdx.x;

    if (blockIdx.x < MROWS) {
        const int row = blockIdx.x;
        const float4* in4 = reinterpret_cast<const float4*>(x + (size_t)row * DD);
        float4* out4 = reinterpret_cast<float4*>(dst + (size_t)row * DD);
        __half2* outh = reinterpret_cast<__half2*>(dsth + (size_t)row * DD);
        const float4* g4 = reinterpret_cast<const float4*>(gamma);
        const float4* b4 = reinterpret_cast<const float4*>(beta);

        float4 xv = in4[tid];
        float s  = xv.x + xv.y + xv.z + xv.w;
        float ss = xv.x * xv.x + xv.y * xv.y + xv.z * xv.z + xv.w * xv.w;
        for (int o = 16; o; o >>= 1) {
            s  += __shfl_xor_sync(0xffffffffu, s, o);
            ss += __shfl_xor_sync(0xffffffffu, ss, o);
        }
        __shared__ float rs[8], rss[8];
        __shared__ float smean, srstd;
        const int warp = tid >> 5, lane = tid & 31;
        if (lane == 0) { rs[warp] = s; rss[warp] = ss; }
        __syncthreads();
        if (warp == 0) {
            float a = (lane < 8) ? rs[lane] : 0.0f;
            float b = (lane < 8) ? rss[lane] : 0.0f;
            for (int o = 4; o; o >>= 1) {
                a += __shfl_xor_sync(0xffffffffu, a, o);
                b += __shfl_xor_sync(0xffffffffu, b, o);
            }
            if (lane == 0) {
                float mean = a * (1.0f / DD);
                float var  = (b - (float)DD * mean * mean) * (1.0f / (DD - 1));
                smean = mean;
                srstd = rsqrtf(var + LN_EPS);
            }
        }
        __syncthreads();
        const float mean = smean, rstd = srstd;
        float4 gv = g4[tid], bv = b4[tid];
        float4 o;
        o.x = (xv.x - mean) * rstd * gv.x + bv.x;
        o.y = (xv.y - mean) * rstd * gv.y + bv.y;
        o.z = (xv.z - mean) * rstd * gv.z + bv.z;
        o.w = (xv.w - mean) * rstd * gv.w + bv.w;
        out4[tid] = o;
        outh[2 * tid]     = __floats2half2_rn(o.x, o.y);
        outh[2 * tid + 1] = __floats2half2_rn(o.z, o.w);
    } else {
        __shared__ float t[32][33];
        const int tblk = blockIdx.x - MROWS;
        const int tx = tid & 31, ty = tid >> 5;

        const float* in; __half* out; int K, N, local;
        if (tblk < 3072) {
            const int seg = tblk >> 10;
            in  = (seg == 0) ? Wq : (seg == 1) ? Wk : Wv;
            out = Wqkv + (size_t)seg * DD * DD;
            K = DD; N = DD; local = tblk & 1023;
        } else if (tblk < 4096) {
            in = Wo; out = WoT; K = DD; N = DD; local = tblk - 3072;
        } else if (tblk < 8192) {
            in = W1; out = W1T; K = DD; N = FF; local = tblk - 4096;
        } else {
            in = W2; out = W2T; K = FF; N = DD; local = tblk - 8192;
        }
        const int ntn = N >> 5;
        const int n0 = (local % ntn) * 32;
        const int k0 = (local / ntn) * 32;

        for (int i = ty; i < 32; i += 8)
            t[i][tx] = in[(size_t)(k0 + i) * N + n0 + tx];
        __syncthreads();
        for (int i = ty; i < 32; i += 8)
            out[(size_t)(n0 + i) * K + k0 + tx] = __float2half_rn(t[tx][i]);
    }
}

// ---------------------------------------------------------------------------
// LayerNorm (unbiased var, ddof=1), dual output: fp32 + half   (LN2)
// ---------------------------------------------------------------------------
__global__ void ln_kernel(const float* __restrict__ src,
                          const float* __restrict__ gamma,
                          const float* __restrict__ beta,
                          float* __restrict__ dst,
                          __half* __restrict__ dsth)
{
    const int row = blockIdx.x;
    const int tid = threadIdx.x;
    const float4* in4 = reinterpret_cast<const float4*>(src + (size_t)row * DD);
    float4* out4 = reinterpret_cast<float4*>(dst + (size_t)row * DD);
    __half2* outh = reinterpret_cast<__half2*>(dsth + (size_t)row * DD);
    const float4* g4 = reinterpret_cast<const float4*>(gamma);
    const float4* b4 = reinterpret_cast<const float4*>(beta);

    float4 x = in4[tid];
    float s  = x.x + x.y + x.z + x.w;
    float ss = x.x * x.x + x.y * x.y + x.z * x.z + x.w * x.w;
    for (int o = 16; o; o >>= 1) {
        s  += __shfl_xor_sync(0xffffffffu, s, o);
        ss += __shfl_xor_sync(0xffffffffu, ss, o);
    }
    __shared__ float rs[8], rss[8];
    __shared__ float smean, srstd;
    const int warp = tid >> 5, lane = tid & 31;
    if (lane == 0) { rs[warp] = s; rss[warp] = ss; }
    __syncthreads();
    if (warp == 0) {
        float a = (lane < 8) ? rs[lane] : 0.0f;
        float b = (lane < 8) ? rss[lane] : 0.0f;
        for (int o = 4; o; o >>= 1) {
            a += __shfl_xor_sync(0xffffffffu, a, o);
            b += __shfl_xor_sync(0xffffffffu, b, o);
        }
        if (lane == 0) {
            float mean = a * (1.0f / DD);
            float var  = (b - (float)DD * mean * mean) * (1.0f / (DD - 1));
            smean = mean;
            srstd = rsqrtf(var + LN_EPS);
        }
    }
    __syncthreads();
    const float mean = smean, rstd = srstd;
    float4 gv = g4[tid], bv = b4[tid];
    float4 o;
    o.x = (x.x - mean) * rstd * gv.x + bv.x;
    o.y = (x.y - mean) * rstd * gv.y + bv.y;
    o.z = (x.z - mean) * rstd * gv.z + bv.z;
    o.w = (x.w - mean) * rstd * gv.w + bv.w;
    out4[tid] = o;
    outh[2 * tid]     = __floats2half2_rn(o.x, o.y);
    outh[2 * tid + 1] = __floats2half2_rn(o.z, o.w);
}

// ---------------------------------------------------------------------------
// fp16 mma GEMM v3: M64 x N128 tile, 8 warps (2m x 4n, warp tile 32x32),
// K-chunk 32, 4-stage prefetch-first cp.async pipeline, ONE barrier/chunk,
// 3 CTAs/SM. Row pitch 80B (stores: 4-phase floor; ldmatrix: 2-phase floor).
// C[M,N] = A[M,K] @ B^T (B [N,K] K-major, half) + bias
// MODE 1: half out, gelu(acc+bias)   MODE 2: float out, acc+bias+Res
// MODE 3: half out, segmented bias (QKV)
// ---------------------------------------------------------------------------
#define GPITCH 80
#define ATILE_B (64 * GPITCH)            // 5120
#define BTILE_B (128 * GPITCH)           // 10240
#define GSTAGE_B (ATILE_B + BTILE_B)     // 15360
#define GNSTAGE 4
#define GSMEM_B (GNSTAGE * GSTAGE_B)     // 61440

template <int MODE>
__global__ __launch_bounds__(256, 3)
void gemm_h(const __half* __restrict__ A, const __half* __restrict__ B,
            const float* __restrict__ bias, void* __restrict__ Cv,
            const float* __restrict__ Res,
            const float* __restrict__ bias2, const float* __restrict__ bias3,
            int M, int N, int K)
{
    extern __shared__ char dynsmem[];
    const int tid = threadIdx.x;
    const int wid = tid >> 5, lane = tid & 31;
    const int bx = blockIdx.x, by = blockIdx.y;

    const int warp_m = (wid & 1) * 32;
    const int warp_n = (wid >> 1) * 32;
    const int lr = lane >> 2;
    const int lc = lane & 3;

    const int lm_m   = lane >> 3;
    const int lm_row = (lm_m & 1) * 8 + (lane & 7);
    const int lm_kb  = (lm_m >> 1) * 16;

    const uint32_t sbase = smem_u32(dynsmem);

    // A staging: 64 rows x 64B; thread -> row=tid/4, part=tid%4 (16B)
    const int a_r = tid >> 2;
    const int a_q = tid & 3;
    const __half* gA = A + (size_t)(by * 64 + a_r) * K + a_q * 8;
    const uint32_t a_off = (uint32_t)(a_r * GPITCH + a_q * 16);
    // B staging: 128 rows x 64B; thread -> row=tid/2, half=tid%2 (32B, 2x16B)
    const int b_r = tid >> 1;
    const int b_h = tid & 1;
    const __half* gB = B + (size_t)(bx * 128 + b_r) * K + b_h * 16;
    const uint32_t b_off = (uint32_t)(b_r * GPITCH + b_h * 32);

    const int NITER = K >> 5;    // K-chunk = 32 halves

    auto stage = [&](int s) {
        const uint32_t base = sbase + (uint32_t)(s & 3) * GSTAGE_B;
        const int k0 = s << 5;
        cp_async16(base + a_off, gA + k0);
        cp_async16(base + ATILE_B + b_off,      gB + k0);
        cp_async16(base + ATILE_B + b_off + 16, gB + k0 + 8);
        CP_COMMIT();
    };

    float c[2][4][4];
#pragma unroll
    for (int mt = 0; mt < 2; mt++)
#pragma unroll
        for (int nt = 0; nt < 4; nt++)
#pragma unroll
            for (int r = 0; r < 4; r++) c[mt][nt][r] = 0.0f;

    stage(0);
    stage(1);
    stage(2);

    for (int i = 0; i < NITER; i++) {
        asm volatile("cp.async.wait_group 2;\n" ::: "memory");
        __syncthreads();

        // prefetch chunk i+3 (buffer (i+3)&3 = (i-1)&3, compute(i-1) done)
        if (i + 3 < NITER) stage(i + 3);
        else               CP_COMMIT();   // keep group accounting uniform

        const uint32_t sA_b = sbase + (uint32_t)(i & 3) * GSTAGE_B;
        const uint32_t sB_b = sA_b + ATILE_B;

#pragma unroll
        for (int ks = 0; ks < 2; ks++) {
            const uint32_t koff = (uint32_t)(ks * 32 + lm_kb);
            uint32_t a[2][4];
            ldsm_x4(a[0], sA_b + (uint32_t)((warp_m + lm_row) * GPITCH) + koff);
            ldsm_x4(a[1], sA_b + (uint32_t)((warp_m + 16 + lm_row) * GPITCH) + koff);
            uint32_t b[4][2];
#pragma unroll
            for (int g = 0; g < 2; g++) {
                uint32_t kf[4];
                ldsm_x4(kf, sB_b + (uint32_t)((warp_n + g * 16 + lm_row) * GPITCH)
                            + koff);
                b[2 * g][0] = kf[0];     b[2 * g][1] = kf[2];
                b[2 * g + 1][0] = kf[1]; b[2 * g + 1][1] = kf[3];
            }
#pragma unroll
            for (int mt = 0; mt < 2; mt++)
#pragma unroll
                for (int nt = 0; nt < 4; nt++)
                    mma_f16(c[mt][nt], a[mt], b[nt]);
        }
    }

    const float* bb = bias;
    if (MODE == 3) {
        const int seg = (bx * 128) >> 10;
        bb = (seg == 0) ? bias : (seg == 1) ? bias2 : bias3;
    }

    const float inv_s2 = 0.70710678118654752f;
    __half* Ch = reinterpret_cast<__half*>(Cv);
    float* Cf = reinterpret_cast<float*>(Cv);
#pragma unroll
    for (int mt = 0; mt < 2; mt++) {
#pragma unroll
        for (int rh = 0; rh < 2; rh++) {
            const int m = by * 64 + warp_m + mt * 16 + lr + rh * 8;
#pragma unroll
            for (int nt = 0; nt < 4; nt++) {
                const int n = bx * 128 + warp_n + nt * 8 + 2 * lc;
                const int nb = (MODE == 3) ? (n & 1023) : n;
                float v0 = c[mt][nt][rh * 2 + 0] + bb[nb];
                float v1 = c[mt][nt][rh * 2 + 1] + bb[nb + 1];
                if (MODE == 1) {
                    v0 = 0.5f * v0 * (1.0f + erff(v0 * inv_s2));
                    v1 = 0.5f * v1 * (1.0f + erff(v1 * inv_s2));
                }
                if (MODE == 2) {
                    float2 rv = *reinterpret_cast<const float2*>(
                        Res + (size_t)m * N + n);
                    v0 += rv.x; v1 += rv.y;
                    *reinterpret_cast<float2*>(Cf + (size_t)m * N + n) =
                        make_float2(v0, v1);
                } else {
                    *reinterpret_cast<__half2*>(Ch + (size_t)m * N + n) =
                        __floats2half2_rn(v0, v1);
                }
            }
        }
    }
}

// ---------------------------------------------------------------------------
// fp16 flash attention (round-9/10 version, 3-buffer prefetch-first pipeline)
// ---------------------------------------------------------------------------
#define AQ_B 18432
#define AKT_B 9216
#define AKV_B (2 * AKT_B)
#define ASMEM_B (AQ_B + 3 * AKV_B)

__global__ __launch_bounds__(256, 2)
void attn_h_kernel(const __half* __restrict__ QKV,
                   __half* __restrict__ O)
{
    extern __shared__ char asmem[];

    const int bh = blockIdx.x;
    const int b  = bh / HH;
    const int h  = bh % HH;
    const int q0 = blockIdx.y * 128;
    const size_t baseq = (size_t)b * TT * QS + (size_t)h * HD;
    const size_t basek = baseq + DD;
    const size_t basev = baseq + 2 * DD;
    const size_t baseo = (size_t)b * TT * DD + (size_t)h * HD;

    const int tid = threadIdx.x;
    const int warp = tid >> 5, lane = tid & 31;
    const int lr = lane >> 2, lc = lane & 3;
    const int qr = warp * 16;

    const uint32_t sQ_b = smem_u32(asmem);
    const uint32_t sB0_b = sQ_b + AQ_B;

    const int lm_m   = lane >> 3;
    const int lm_row = (lm_m & 1) * 8 + (lane & 7);
    const int lm_kb  = (lm_m >> 1) * 16;

    const int st_r = tid >> 2;
    const int st_q = tid & 3;
    auto stage_tile = [&](uint32_t dstbase, const __half* gsrc) {
        const uint32_t d = dstbase + (uint32_t)(st_r * 144 + st_q * 32);
        const __half* g = gsrc + (size_t)st_r * QS + st_q * 16;
        cp_async16(d, g);
        cp_async16(d + 16, g + 8);
    };

    stage_tile(sQ_b,         QKV + baseq + (size_t)q0 * QS);
    stage_tile(sQ_b + AKT_B, QKV + baseq + (size_t)(q0 + 64) * QS);
    stage_tile(sB0_b,         QKV + basek);
    stage_tile(sB0_b + AKT_B, QKV + basev);
    CP_COMMIT();
    stage_tile(sB0_b + AKV_B,         QKV + basek + (size_t)64 * QS);
    stage_tile(sB0_b + AKV_B + AKT_B, QKV + basev + (size_t)64 * QS);
    CP_COMMIT();

    float m0 = -INFINITY, m1 = -INFINITY;
    float l0 = 0.0f, l1 = 0.0f;
    float o[8][4];
#pragma unroll
    for (int nt = 0; nt < 8; nt++)
#pragma unroll
        for (int j = 0; j < 4; j++) o[nt][j] = 0.0f;

    uint32_t qf[4][4];

    const int NT = TT / 64;
    for (int t = 0; t < NT; t++) {
        if (t < NT - 1)
            asm volatile("cp.async.wait_group 1;\n" ::: "memory");
        else
            asm volatile("cp.async.wait_group 0;\n" ::: "memory");
        __syncthreads();

        if (t + 2 < NT) {
            const uint32_t dst = sB0_b + (uint32_t)((t + 2) % 3) * AKV_B;
            stage_tile(dst,         QKV + basek + (size_t)((t + 2) * 64) * QS);
            stage_tile(dst + AKT_B, QKV + basev + (size_t)((t + 2) * 64) * QS);
            CP_COMMIT();
        }

        if (t == 0) {
#pragma unroll
            for (int ks = 0; ks < 4; ks++)
                ldsm_x4(qf[ks], sQ_b + (uint32_t)((qr + lm_row) * 144 +
                                                  ks * 32 + lm_kb));
        }

        const uint32_t sK_b = sB0_b + (uint32_t)(t % 3) * AKV_B;
        const uint32_t sV_b = sK_b + AKT_B;

        float s[8][4];
#pragma unroll
        for (int nt = 0; nt < 8; nt++)
#pragma unroll
            for (int j = 0; j < 4; j++) s[nt][j] = 0.0f;

#pragma unroll
        for (int ks = 0; ks < 4; ks++) {
#pragma unroll
            for (int g = 0; g < 4; g++) {
                uint32_t kf[4];
                ldsm_x4(kf, sK_b + (uint32_t)((g * 16 + lm_row) * 144 +
                                              ks * 32 + lm_kb));
                uint32_t b0[2] = {kf[0], kf[2]};
                uint32_t b1[2] = {kf[1], kf[3]};
                mma_f16(s[2 * g],     qf[ks], b0);
                mma_f16(s[2 * g + 1], qf[ks], b1);
            }
        }

        float mx0 = -INFINITY, mx1 = -INFINITY;
#pragma unroll
        for (int nt = 0; nt < 8; nt++) {
            s[nt][0] *= 0.125f; s[nt][1] *= 0.125f;
            s[nt][2] *= 0.125f; s[nt][3] *= 0.125f;
            mx0 = fmaxf(mx0, fmaxf(s[nt][0], s[nt][1]));
            mx1 = fmaxf(mx1, fmaxf(s[nt][2], s[nt][3]));
        }
        mx0 = fmaxf(mx0, __shfl_xor_sync(0xffffffffu, mx0, 1));
        mx0 = fmaxf(mx0, __shfl_xor_sync(0xffffffffu, mx0, 2));
        mx1 = fmaxf(mx1, __shfl_xor_sync(0xffffffffu, mx1, 1));
        mx1 = fmaxf(mx1, __shfl_xor_sync(0xffffffffu, mx1, 2));

        const float nm0 = fmaxf(m0, mx0), nm1 = fmaxf(m1, mx1);
        const float corr0 = __expf(m0 - nm0), corr1 = __expf(m1 - nm1);
        m0 = nm0; m1 = nm1;

        float ls0 = 0.0f, ls1 = 0.0f;
#pragma unroll
        for (int nt = 0; nt < 8; nt++) {
            s[nt][0] = __expf(s[nt][0] - nm0);
            s[nt][1] = __expf(s[nt][1] - nm0);
            s[nt][2] = __expf(s[nt][2] - nm1);
            s[nt][3] = __expf(s[nt][3] - nm1);
            ls0 += s[nt][0] + s[nt][1];
            ls1 += s[nt][2] + s[nt][3];
        }
        ls0 += __shfl_xor_sync(0xffffffffu, ls0, 1);
        ls0 += __shfl_xor_sync(0xffffffffu, ls0, 2);
        ls1 += __shfl_xor_sync(0xffffffffu, ls1, 1);
        ls1 += __shfl_xor_sync(0xffffffffu, ls1, 2);
        l0 = l0 * corr0 + ls0;
        l1 = l1 * corr1 + ls1;

#pragma unroll
        for (int nt = 0; nt < 8; nt++) {
            o[nt][0] *= corr0; o[nt][1] *= corr0;
            o[nt][2] *= corr1; o[nt][3] *= corr1;
        }

        const int key = (lane & 7) + ((lane >> 3) & 1) * 8;
#pragma unroll
        for (int ks = 0; ks < 4; ks++) {
            uint32_t pa[4];
            __half2 hh;
            hh = __floats2half2_rn(s[2 * ks][0], s[2 * ks][1]);
            pa[0] = *reinterpret_cast<uint32_t*>(&hh);
            hh = __floats2half2_rn(s[2 * ks][2], s[2 * ks][3]);
            pa[1] = *reinterpret_cast<uint32_t*>(&hh);
            hh = __floats2half2_rn(s[2 * ks + 1][0], s[2 * ks + 1][1]);
            pa[2] = *reinterpret_cast<uint32_t*>(&hh);
            hh = __floats2half2_rn(s[2 * ks + 1][2], s[2 * ks + 1][3]);
            pa[3] = *reinterpret_cast<uint32_t*>(&hh);

#pragma unroll
            for (int ntp = 0; ntp < 4; ntp++) {
                uint32_t r[4];
                const uint32_t addr = sV_b +
                    (uint32_t)((ks * 16 + key) * 144 + ntp * 32 +
                               ((lane >> 4) & 1) * 16);
                ldsm_x4_trans(r, addr);
                uint32_t b0[2] = {r[0], r[1]};
                uint32_t b1[2] = {r[2], r[3]};
                mma_f16(o[2 * ntp],     pa, b0);
                mma_f16(o[2 * ntp + 1], pa, b1);
            }
        }
    }

    const float inv0 = 1.0f / l0, inv1 = 1.0f / l1;
    const size_t row0 = baseo + (size_t)(q0 + qr + lr) * DD;
    const size_t row1 = baseo + (size_t)(q0 + qr + lr + 8) * DD;
#pragma unroll
    for (int nt = 0; nt < 8; nt++) {
        const int col = nt * 8 + 2 * lc;
        *reinterpret_cast<__half2*>(O + row0 + col) =
            __floats2half2_rn(o[nt][0] * inv0, o[nt][1] * inv0);
        *reinterpret_cast<__half2*>(O + row1 + col) =
            __floats2half2_rn(o[nt][2] * inv1, o[nt][3] * inv1);
    }
}

// ---------------------------------------------------------------------------
// Launch
// ---------------------------------------------------------------------------
template <typename T>
static T* symT(const void* symbol)
{
    void* p = nullptr;
    cudaGetSymbolAddress(&p, symbol);
    return reinterpret_cast<T*>(p);
}

extern "C" void kernel_launch(void* const* d_in, const int* in_sizes, int n_in,
                              void* d_out, int out_size)
{
    const float* x  = (const float*)d_in[0];
    const float* Wq = (const float*)d_in[1];  const float* bq = (const float*)d_in[2];
    const float* Wk = (const float*)d_in[3];  const float* bk = (const float*)d_in[4];
    const float* Wv = (const float*)d_in[5];  const float* bv = (const float*)d_in[6];
    const float* Wo = (const float*)d_in[7];  const float* bo = (const float*)d_in[8];
    const float* W1 = (const float*)d_in[9];  const float* b1 = (const float*)d_in[10];
    const float* W2 = (const float*)d_in[11]; const float* b2 = (const float*)d_in[12];
    const float* g1 = (const float*)d_in[13]; const float* be1 = (const float*)d_in[14];
    const float* g2 = (const float*)d_in[15]; const float* be2 = (const float*)d_in[16];
    float* out = (float*)d_out;

    float*  hln1  = symT<float>(g_hln1);
    __half* hln1t = symT<__half>(g_hln1t);
    __half* qkv   = symT<__half>(g_qkv);
    __half* ctx   = symT<__half>(g_ctx);
    float*  hb    = symT<float>(g_h);
    float*  h2b   = symT<float>(g_h2);
    __half* h2t   = symT<__half>(g_h2t);
    __half* ffb   = symT<__half>(g_ff);
    __half* Wqkv = symT<__half>(g_Wqkv);
    __half* WoT  = symT<__half>(g_WoT);
    __half* W1T  = symT<__half>(g_W1T);
    __half* W2T  = symT<__half>(g_W2T);

    cudaFuncSetAttribute(gemm_h<1>, cudaFuncAttributeMaxDynamicSharedMemorySize, GSMEM_B);
    cudaFuncSetAttribute(gemm_h<2>, cudaFuncAttributeMaxDynamicSharedMemorySize, GSMEM_B);
    cudaFuncSetAttribute(gemm_h<3>, cudaFuncAttributeMaxDynamicSharedMemorySize, GSMEM_B);
    cudaFuncSetAttribute(attn_h_kernel, cudaFuncAttributeMaxDynamicSharedMemorySize, ASMEM_B);

    // 0+1. fused prep: LN1 + all weight transposes
    prep_kernel<<<MROWS + 12288, 256>>>(
        x, g1, be1, hln1, hln1t,
        Wq, Wk, Wv, Wo, W1, W2, Wqkv, WoT, W1T, W2T);

    // 2. fused QKV projection -> packed [M][3072]
    {
        dim3 grid(QS / 128, MROWS / 64);
        gemm_h<3><<<grid, 256, GSMEM_B>>>(hln1t, Wqkv, bq, qkv, nullptr,
                                          bk, bv, MROWS, QS, DD);
    }

    // 3. attention (128 q-rows per block, 8 warps)
    {
        dim3 grid(BB * HH, TT / 128);
        attn_h_kernel<<<grid, 256, ASMEM_B>>>(qkv, ctx);
    }

    // 4. output projection + residual (fp32 out)
    {
        dim3 grid(DD / 128, MROWS / 64);
        gemm_h<2><<<grid, 256, GSMEM_B>>>(ctx, WoT, bo, hb, hln1,
                                          nullptr, nullptr, MROWS, DD, DD);
    }

    // 5. LN2
    ln_kernel<<<MROWS, 256>>>(hb, g2, be2, h2b, h2t);

    // 6. FFN up + exact GELU (half out)
    {
        dim3 grid(FF / 128, MROWS / 64);
        gemm_h<1><<<grid, 256, GSMEM_B>>>(h2t, W1T, b1, ffb, nullptr,
                                          nullptr, nullptr, MROWS, FF, DD);
    }

    // 7. FFN down + bias + residual -> out (fp32)
    {
        dim3 grid(DD / 128, MROWS / 64);
        gemm_h<2><<<grid, 256, GSMEM_B>>>(ffb, W2T, b2, out, h2b,
                                          nullptr, nullptr, MROWS, DD, FF);
    }
}